// round 4
// baseline (speedup 1.0000x reference)
#include <cuda_runtime.h>
#include <cstdint>

#define T_STEPS 100
#define B 16
#define E 128
#define H 256
#define L 2048

// ---------------- device scratch (static allocations only) ----------------
__device__ float g_enc_feat[B * L * H];          // 33.5 MB
__device__ float g_WhT[512 * 256];               // Wh transposed [k][n]
__device__ float g_x_all[T_STEPS * B * E];       // x_t for every step
__device__ float g_gi[T_STEPS * B * 4 * H];      // x_t @ Wih.T + bih + bhh
__device__ float g_h[2][B * H];
__device__ float g_c[2][B * H];
__device__ float g_dec[B * H];
__device__ float g_ctx[B * 2 * H];

// ---------------- fast math helpers ----------------
__device__ __forceinline__ float tanh_f(float x) {
    float e = __expf(2.f * x);
    return 1.f - __fdividef(2.f, e + 1.f);
}
__device__ __forceinline__ float sig_f(float x) {
    return __fdividef(1.f, 1.f + __expf(-x));
}
__device__ __forceinline__ float wreduce(float s) {
    #pragma unroll
    for (int off = 16; off; off >>= 1) s += __shfl_xor_sync(0xffffffffu, s, off);
    return s;
}

// ---------------- pre-kernel 0: transpose Wh + init h/c ----------------
__global__ void k_pre0(const float* __restrict__ Wh,
                       const float* __restrict__ h0, const float* __restrict__ c0) {
    int i = blockIdx.x * 256 + threadIdx.x;   // i = k*256 + n, 131072 total
    int n = i & 255, k = i >> 8;
    g_WhT[i] = Wh[n * 512 + k];
    if (i < B * H) {
        g_h[0][i] = h0[i];
        g_c[0][i] = c0[i];
    }
}

// ---------------- pre-kernel 1: x_all and gi (input-dependent only) --------
__global__ void k_pre_x(const float* __restrict__ dec_in,
                        const float* __restrict__ Wx, const float* __restrict__ bx,
                        const float* __restrict__ Wih, const float* __restrict__ bih,
                        const float* __restrict__ bhh) {
    __shared__ float s_in[E];
    __shared__ float s_x[E];
    int r = blockIdx.x;   // r = t*B + b
    int tid = threadIdx.x;
    if (tid < E) s_in[tid] = dec_in[r * E + tid];
    __syncthreads();
    if (tid < E) {
        int j = tid;
        const float* w = Wx + j * (2 * H + E);   // only first E cols matter (ctx is zero)
        float s = bx[j];
        #pragma unroll 4
        for (int k = 0; k < E; k++) s += s_in[k] * w[k];
        s_x[j] = s;
        g_x_all[r * E + j] = s;
    }
    __syncthreads();
    for (int j = tid; j < 4 * H; j += 256) {
        const float* w = Wih + j * E;
        float s = bih[j] + bhh[j];
        #pragma unroll 4
        for (int k = 0; k < E; k++) s += s_x[k] * w[k];
        g_gi[r * 4 * H + j] = s;
    }
}

// ---------------- pre-kernel 2: enc_feat = enc_states @ Wh.T + bh ----------
__global__ void k_encfeat(const float* __restrict__ ES, const float* __restrict__ bh) {
    __shared__ float As[64][17];
    __shared__ float Bs[16][64];
    int m0 = blockIdx.y * 64;
    int n0 = blockIdx.x * 64;
    int tx = threadIdx.x & 15, ty = threadIdx.x >> 4;
    float acc[4][4] = {};
    for (int k0 = 0; k0 < 512; k0 += 16) {
        for (int i = threadIdx.x; i < 64 * 16; i += 256) {
            int m = i >> 4, k = i & 15;
            As[m][k] = ES[(size_t)(m0 + m) * 512 + k0 + k];
        }
        for (int i = threadIdx.x; i < 16 * 64; i += 256) {
            int k = i >> 6, n = i & 63;
            Bs[k][n] = g_WhT[(k0 + k) * 256 + n0 + n];
        }
        __syncthreads();
        #pragma unroll
        for (int kk = 0; kk < 16; kk++) {
            float a0 = As[ty * 4 + 0][kk];
            float a1 = As[ty * 4 + 1][kk];
            float a2 = As[ty * 4 + 2][kk];
            float a3 = As[ty * 4 + 3][kk];
            float4 b4 = *(const float4*)&Bs[kk][tx * 4];
            acc[0][0] += a0 * b4.x; acc[0][1] += a0 * b4.y; acc[0][2] += a0 * b4.z; acc[0][3] += a0 * b4.w;
            acc[1][0] += a1 * b4.x; acc[1][1] += a1 * b4.y; acc[1][2] += a1 * b4.z; acc[1][3] += a1 * b4.w;
            acc[2][0] += a2 * b4.x; acc[2][1] += a2 * b4.y; acc[2][2] += a2 * b4.z; acc[2][3] += a2 * b4.w;
            acc[3][0] += a3 * b4.x; acc[3][1] += a3 * b4.y; acc[3][2] += a3 * b4.z; acc[3][3] += a3 * b4.w;
        }
        __syncthreads();
    }
    #pragma unroll
    for (int i = 0; i < 4; i++) {
        int m = m0 + ty * 4 + i;
        #pragma unroll
        for (int j = 0; j < 4; j++) {
            int n = n0 + tx * 4 + j;
            g_enc_feat[(size_t)m * 256 + n] = acc[i][j] + bh[n];
        }
    }
}

// ---------------- per-step kernel 1: epilogue(t-1) + LSTM(t) + dec_feat(t) --
// grid = 16 blocks (one per batch elem), 256 threads (8 warps).
// t ranges 0..100; t==100 is the tail call (epilogue for step 99 + h_f/c_f).
__global__ void __launch_bounds__(256)
k_step1(int t,
        const float* __restrict__ Whh,
        const float* __restrict__ Ws_, const float* __restrict__ bs_,
        const float* __restrict__ Wout, const float* __restrict__ bout,
        const float* __restrict__ Wpg, const float* __restrict__ bpg,
        float* __restrict__ o_out, float* __restrict__ o_pgen,
        float* __restrict__ o_hf, float* __restrict__ o_cf) {
    __shared__ float s_h[H], s_c[H], s_ctx[2 * H], s_hn[H], s_cn[H];
    const int b = blockIdx.x, tid = threadIdx.x;
    const int lane = tid & 31, wid = tid >> 5;
    const int par = t & 1;

    s_h[tid] = g_h[par][b * H + tid];
    s_c[tid] = g_c[par][b * H + tid];
    if (t > 0) {
        s_ctx[tid] = g_ctx[b * 2 * H + tid];
        s_ctx[H + tid] = g_ctx[b * 2 * H + H + tid];
    }
    __syncthreads();

    if (t > 0) {
        // ---- out[t-1] = [h(t-1), ctx(t-1)] @ Wout.T + bout ----
        for (int j = wid; j < H; j += 8) {
            const float* w = Wout + (size_t)j * (3 * H);
            float s = 0.f;
            #pragma unroll
            for (int i = 0; i < 8; i++) {
                int k = lane + i * 32;
                s += s_h[k] * w[k];
            }
            #pragma unroll
            for (int i = 0; i < 16; i++) {
                int k = lane + i * 32;
                s += s_ctx[k] * w[H + k];
            }
            s = wreduce(s);
            if (lane == 0) o_out[((size_t)((t - 1) * B + b)) * H + j] = s + bout[j];
        }
        // ---- p_gen[t-1] = sigmoid([ctx, h, c, x] @ Wpg.T + bpg) ----
        if (wid == 0) {
            float s = 0.f;
            for (int k = lane; k < 4 * H + E; k += 32) {
                float cv;
                if (k < 2 * H) cv = s_ctx[k];
                else if (k < 3 * H) cv = s_h[k - 2 * H];
                else if (k < 4 * H) cv = s_c[k - 3 * H];
                else cv = g_x_all[((t - 1) * B + b) * E + k - 4 * H];
                s += cv * Wpg[k];
            }
            s = wreduce(s);
            if (lane == 0) o_pgen[(t - 1) * B + b] = sig_f(s + bpg[0]);
        }
    }

    if (t == T_STEPS) {
        // tail: h_f, c_f = h(99), c(99)  (par = 100&1 = 0 holds them)
        o_hf[b * H + tid] = s_h[tid];
        o_cf[b * H + tid] = s_c[tid];
        return;
    }

    // ---- LSTM gates: warp-per-unit j, 4 gate dots over K=256 ----
    const float* gi = g_gi + (size_t)(t * B + b) * 4 * H;
    for (int j = wid; j < H; j += 8) {
        float hk[8];
        #pragma unroll
        for (int i = 0; i < 8; i++) hk[i] = s_h[lane + i * 32];
        float acc[4];
        #pragma unroll
        for (int g = 0; g < 4; g++) {
            const float* w = Whh + (size_t)(g * H + j) * H;
            float s = 0.f;
            #pragma unroll
            for (int i = 0; i < 8; i++) s += hk[i] * w[lane + i * 32];
            acc[g] = wreduce(s);
        }
        if (lane == 0) {
            float ig = acc[0] + gi[j];
            float fg = acc[1] + gi[H + j];
            float gg = acc[2] + gi[2 * H + j];
            float og = acc[3] + gi[3 * H + j];
            float cn = sig_f(fg) * s_c[j] + sig_f(ig) * tanh_f(gg);
            float hn = sig_f(og) * tanh_f(cn);
            s_cn[j] = cn;
            s_hn[j] = hn;
            g_c[par ^ 1][b * H + j] = cn;
            g_h[par ^ 1][b * H + j] = hn;
        }
    }
    __syncthreads();

    // ---- dec_feat = [h_new, c_new] @ Ws.T + bs ----
    for (int j = wid; j < H; j += 8) {
        const float* w = Ws_ + (size_t)j * (2 * H);
        float s = 0.f;
        #pragma unroll
        for (int i = 0; i < 8; i++) {
            int k = lane + i * 32;
            s += s_hn[k] * w[k];
            s += s_cn[k] * w[H + k];
        }
        s = wreduce(s);
        if (lane == 0) g_dec[b * H + j] = s + bs_[j];
    }
}

// ---------------- per-step kernel 2: e[b,l] = sum_h v*tanh(enc_feat+dec) ----
// grid = 256 blocks x 256 threads = 2048 warps; 128 warps per b, 16 rows/warp.
__global__ void __launch_bounds__(256)
k_escore(int t, const float* __restrict__ v, float* __restrict__ o_attn) {
    const int tid = threadIdx.x;
    const int lane = tid & 31, wid = tid >> 5;
    const int gwarp = blockIdx.x * 8 + wid;
    const int b = gwarp >> 7;          // 128 warps per batch elem
    const int ww = gwarp & 127;

    // per-warp constants: dec[b, lane*8..+7] and v[lane*8..+7]
    const float4* d4 = (const float4*)(g_dec + b * H);
    const float4* v4 = (const float4*)v;
    float4 dfa = d4[lane * 2], dfb = d4[lane * 2 + 1];
    float4 sva = v4[lane * 2], svb = v4[lane * 2 + 1];

    float* e_out = o_attn + (size_t)t * B * L;
    for (int r = 0; r < 16; r++) {
        int l = ww * 16 + r;
        const float4* ef = (const float4*)(g_enc_feat + ((size_t)(b * L + l)) * H);
        float4 ea = ef[lane * 2], eb = ef[lane * 2 + 1];
        float s = sva.x * tanh_f(ea.x + dfa.x)
                + sva.y * tanh_f(ea.y + dfa.y)
                + sva.z * tanh_f(ea.z + dfa.z)
                + sva.w * tanh_f(ea.w + dfa.w)
                + svb.x * tanh_f(eb.x + dfb.x)
                + svb.y * tanh_f(eb.y + dfb.y)
                + svb.z * tanh_f(eb.z + dfb.z)
                + svb.w * tanh_f(eb.w + dfb.w);
        s = wreduce(s);
        if (lane == 0) e_out[b * L + l] = s;
    }
}

// ---------------- per-step kernel 3: masked softmax in-place + zero ctx -----
// grid = 16 blocks (one per b), 256 threads; 8 elems/thread.
__global__ void __launch_bounds__(256)
k_softmax(int t, const float* __restrict__ mask, float* __restrict__ o_attn) {
    __shared__ float scr[16];
    const int b = blockIdx.x, tid = threadIdx.x;
    const int lane = tid & 31, wid = tid >> 5;

    g_ctx[b * 2 * H + tid] = 0.f;
    g_ctx[b * 2 * H + H + tid] = 0.f;

    float* row = o_attn + ((size_t)(t * B + b)) * L;
    const float* mrow = mask + (size_t)b * L;

    float ev[8], mv[8];
    float mx = -3.4e38f;
    #pragma unroll
    for (int i = 0; i < 8; i++) {
        ev[i] = row[tid + i * 256];
        mv[i] = mrow[tid + i * 256];
        mx = fmaxf(mx, ev[i]);
    }
    #pragma unroll
    for (int off = 16; off; off >>= 1) mx = fmaxf(mx, __shfl_xor_sync(0xffffffffu, mx, off));
    if (lane == 0) scr[wid] = mx;
    __syncthreads();
    mx = scr[0];
    #pragma unroll
    for (int i = 1; i < 8; i++) mx = fmaxf(mx, scr[i]);

    float pv[8];
    float s = 0.f;
    #pragma unroll
    for (int i = 0; i < 8; i++) {
        pv[i] = __expf(ev[i] - mx) * mv[i];
        s += pv[i];
    }
    s = wreduce(s);
    if (lane == 0) scr[8 + wid] = s;
    __syncthreads();
    s = 0.f;
    #pragma unroll
    for (int i = 0; i < 8; i++) s += scr[8 + i];
    float inv = __fdividef(1.f, s);
    #pragma unroll
    for (int i = 0; i < 8; i++) row[tid + i * 256] = pv[i] * inv;
}

// ---------------- per-step kernel 4: ctx = attn @ encoder_states -----------
// grid = 256 blocks: b = blk>>4, chunk = blk&15 (128 l-rows each); atomics.
__global__ void __launch_bounds__(256)
k_ctx(int t, const float* __restrict__ enc, const float* __restrict__ o_attn) {
    __shared__ float sa[128];
    const int b = blockIdx.x >> 4, ch = blockIdx.x & 15;
    const int l0 = ch * 128;
    const int tid = threadIdx.x;

    if (tid < 128) sa[tid] = o_attn[((size_t)(t * B + b)) * L + l0 + tid];
    __syncthreads();

    const int d = tid * 2;
    const float* es = enc + ((size_t)(b * L + l0)) * (2 * H) + d;
    float ax = 0.f, ay = 0.f;
    #pragma unroll 4
    for (int i = 0; i < 128; i++) {
        float a = sa[i];
        float2 s2 = *(const float2*)(es + (size_t)i * (2 * H));
        ax += a * s2.x;
        ay += a * s2.y;
    }
    atomicAdd(&g_ctx[b * 2 * H + d], ax);
    atomicAdd(&g_ctx[b * 2 * H + d + 1], ay);
}

// ---------------- host launcher ----------------
extern "C" void kernel_launch(void* const* d_in, const int* in_sizes, int n_in,
                              void* d_out, int out_size) {
    const float* dec_in = (const float*)d_in[0];
    const float* h0     = (const float*)d_in[1];
    const float* c0     = (const float*)d_in[2];
    const float* enc    = (const float*)d_in[3];
    const float* mask   = (const float*)d_in[4];
    const float* Wh     = (const float*)d_in[5];
    const float* bh     = (const float*)d_in[6];
    const float* Ws_    = (const float*)d_in[7];
    const float* bs_    = (const float*)d_in[8];
    const float* v      = (const float*)d_in[9];
    const float* Wx     = (const float*)d_in[10];
    const float* bx     = (const float*)d_in[11];
    const float* Wih    = (const float*)d_in[12];
    const float* bih    = (const float*)d_in[13];
    const float* Whh    = (const float*)d_in[14];
    const float* bhh    = (const float*)d_in[15];
    const float* Wpg    = (const float*)d_in[16];
    const float* bpg    = (const float*)d_in[17];
    const float* Wout   = (const float*)d_in[18];
    const float* bout   = (const float*)d_in[19];

    float* out = (float*)d_out;
    float* o_outputs = out;                                  // [T,B,H]
    float* o_hf = o_outputs + (size_t)T_STEPS * B * H;       // [B,H]
    float* o_cf = o_hf + B * H;                              // [B,H]
    float* o_attn = o_cf + B * H;                            // [T,B,L]
    float* o_pgen = o_attn + (size_t)T_STEPS * B * L;        // [T,B,1]

    k_pre0<<<512, 256>>>(Wh, h0, c0);
    k_pre_x<<<T_STEPS * B, 256>>>(dec_in, Wx, bx, Wih, bih, bhh);
    k_encfeat<<<dim3(4, 512), 256>>>(enc, bh);

    for (int t = 0; t < T_STEPS; t++) {
        k_step1<<<B, 256>>>(t, Whh, Ws_, bs_, Wout, bout, Wpg, bpg,
                            o_outputs, o_pgen, o_hf, o_cf);
        k_escore<<<256, 256>>>(t, v, o_attn);
        k_softmax<<<B, 256>>>(t, mask, o_attn);
        k_ctx<<<256, 256>>>(t, enc, o_attn);
    }
    // tail: epilogue for step 99 + h_f/c_f
    k_step1<<<B, 256>>>(T_STEPS, Whh, Ws_, bs_, Wout, bout, Wpg, bpg,
                        o_outputs, o_pgen, o_hf, o_cf);
}

// round 5
// speedup vs baseline: 2.3950x; 2.3950x over previous
#include <cuda_runtime.h>
#include <cstdint>

#define T_STEPS 100
#define B 16
#define E 128
#define H 256
#define L 2048

// ---------------- device scratch (static allocations only) ----------------
__device__ float g_enc_feat[B * L * H];          // 33.5 MB
__device__ float g_WhT[512 * 256];               // Wh transposed [k][n]
__device__ float g_x_all[T_STEPS * B * E];       // x_t for every step
__device__ float g_gi[T_STEPS * B * 4 * H];      // x_t @ Wih.T + bih + bhh
__device__ float g_h[2][B * H];
__device__ float g_c[2][B * H];
__device__ float g_dec[B * H];
__device__ float g_ctx[B * 2 * H];

// ---------------- fast math helpers ----------------
__device__ __forceinline__ float tanh_f(float x) {
    float e = __expf(2.f * x);
    return 1.f - __fdividef(2.f, e + 1.f);
}
__device__ __forceinline__ float sig_f(float x) {
    return __fdividef(1.f, 1.f + __expf(-x));
}
__device__ __forceinline__ float wreduce(float s) {
    #pragma unroll
    for (int off = 16; off; off >>= 1) s += __shfl_xor_sync(0xffffffffu, s, off);
    return s;
}

// ---------------- pre-kernel 0: transpose Wh + init h/c ----------------
__global__ void k_pre0(const float* __restrict__ Wh,
                       const float* __restrict__ h0, const float* __restrict__ c0) {
    int i = blockIdx.x * 256 + threadIdx.x;   // i = k*256 + n, 131072 total
    int n = i & 255, k = i >> 8;
    g_WhT[i] = Wh[n * 512 + k];
    if (i < B * H) {
        g_h[0][i] = h0[i];
        g_c[0][i] = c0[i];
    }
}

// ---------------- pre-kernel 1: x_all and gi (input-dependent only) --------
__global__ void k_pre_x(const float* __restrict__ dec_in,
                        const float* __restrict__ Wx, const float* __restrict__ bx,
                        const float* __restrict__ Wih, const float* __restrict__ bih,
                        const float* __restrict__ bhh) {
    __shared__ float s_in[E];
    __shared__ float s_x[E];
    int r = blockIdx.x;   // r = t*B + b
    int tid = threadIdx.x;
    if (tid < E) s_in[tid] = dec_in[r * E + tid];
    __syncthreads();
    if (tid < E) {
        int j = tid;
        const float* w = Wx + j * (2 * H + E);   // only first E cols matter (ctx is zero)
        float s = bx[j];
        #pragma unroll 4
        for (int k = 0; k < E; k++) s += s_in[k] * w[k];
        s_x[j] = s;
        g_x_all[r * E + j] = s;
    }
    __syncthreads();
    for (int j = tid; j < 4 * H; j += 256) {
        const float* w = Wih + j * E;
        float s = bih[j] + bhh[j];
        #pragma unroll 4
        for (int k = 0; k < E; k++) s += s_x[k] * w[k];
        g_gi[r * 4 * H + j] = s;
    }
}

// ---------------- pre-kernel 2: enc_feat = enc_states @ Wh.T + bh ----------
__global__ void k_encfeat(const float* __restrict__ ES, const float* __restrict__ bh) {
    __shared__ float As[64][17];
    __shared__ float Bs[16][64];
    int m0 = blockIdx.y * 64;
    int n0 = blockIdx.x * 64;
    int tx = threadIdx.x & 15, ty = threadIdx.x >> 4;
    float acc[4][4] = {};
    for (int k0 = 0; k0 < 512; k0 += 16) {
        for (int i = threadIdx.x; i < 64 * 16; i += 256) {
            int m = i >> 4, k = i & 15;
            As[m][k] = ES[(size_t)(m0 + m) * 512 + k0 + k];
        }
        for (int i = threadIdx.x; i < 16 * 64; i += 256) {
            int k = i >> 6, n = i & 63;
            Bs[k][n] = g_WhT[(k0 + k) * 256 + n0 + n];
        }
        __syncthreads();
        #pragma unroll
        for (int kk = 0; kk < 16; kk++) {
            float a0 = As[ty * 4 + 0][kk];
            float a1 = As[ty * 4 + 1][kk];
            float a2 = As[ty * 4 + 2][kk];
            float a3 = As[ty * 4 + 3][kk];
            float4 b4 = *(const float4*)&Bs[kk][tx * 4];
            acc[0][0] += a0 * b4.x; acc[0][1] += a0 * b4.y; acc[0][2] += a0 * b4.z; acc[0][3] += a0 * b4.w;
            acc[1][0] += a1 * b4.x; acc[1][1] += a1 * b4.y; acc[1][2] += a1 * b4.z; acc[1][3] += a1 * b4.w;
            acc[2][0] += a2 * b4.x; acc[2][1] += a2 * b4.y; acc[2][2] += a2 * b4.z; acc[2][3] += a2 * b4.w;
            acc[3][0] += a3 * b4.x; acc[3][1] += a3 * b4.y; acc[3][2] += a3 * b4.z; acc[3][3] += a3 * b4.w;
        }
        __syncthreads();
    }
    #pragma unroll
    for (int i = 0; i < 4; i++) {
        int m = m0 + ty * 4 + i;
        #pragma unroll
        for (int j = 0; j < 4; j++) {
            int n = n0 + tx * 4 + j;
            g_enc_feat[(size_t)m * 256 + n] = acc[i][j] + bh[n];
        }
    }
}

// ================= per-step kernel A =================
// grid = 66 blocks x 256 threads.
//   blocks  0-31 : LSTM gates (warp per output unit j, batch loop in regs)
//   blocks 32-63 : out[t-1] = [h(t-1), ctx(t-1)] @ Wout.T + bout
//   blocks 64-65 : p_gen[t-1]; at t==T_STEPS also copy h_f/c_f
__global__ void __launch_bounds__(256)
k_A(int t,
    const float* __restrict__ Whh,
    const float* __restrict__ Wout, const float* __restrict__ bout,
    const float* __restrict__ Wpg, const float* __restrict__ bpg,
    float* __restrict__ o_out, float* __restrict__ o_pgen,
    float* __restrict__ o_hf, float* __restrict__ o_cf) {
    __shared__ float sbuf[12288];   // 48 KB
    const int blk = blockIdx.x, tid = threadIdx.x;
    const int lane = tid & 31, wid = tid >> 5;
    const int par = t & 1;

    if (blk < 32) {
        // ---- LSTM gates: warp owns unit j for all 16 batches ----
        if (t == T_STEPS) return;
        // stage h(t-1): 4096 floats
        for (int i = tid; i < B * H; i += 256) sbuf[i] = g_h[par][i];
        __syncthreads();

        const int j = blk * 8 + wid;
        float w[4][8];
        #pragma unroll
        for (int g = 0; g < 4; g++)
            #pragma unroll
            for (int i = 0; i < 8; i++)
                w[g][i] = Whh[(size_t)(g * H + j) * H + lane + i * 32];

        // lane b (<16) preloads its batch's c_old and 4 gi values
        float cold = 0.f, gi0 = 0.f, gi1 = 0.f, gi2 = 0.f, gi3 = 0.f;
        if (lane < B) {
            cold = g_c[par][lane * H + j];
            const float* gi = g_gi + (size_t)(t * B + lane) * 4 * H;
            gi0 = gi[j]; gi1 = gi[H + j]; gi2 = gi[2 * H + j]; gi3 = gi[3 * H + j];
        }

        float acc[4];
        #pragma unroll 1
        for (int b = 0; b < B; b++) {
            const float* hb = sbuf + b * H;
            #pragma unroll
            for (int g = 0; g < 4; g++) {
                float s = 0.f;
                #pragma unroll
                for (int i = 0; i < 8; i++) s += w[g][i] * hb[lane + i * 32];
                acc[g] = wreduce(s);   // butterfly: result in all lanes
            }
            if (lane == b) {
                float ig = acc[0] + gi0;
                float fg = acc[1] + gi1;
                float gg = acc[2] + gi2;
                float og = acc[3] + gi3;
                float cn = sig_f(fg) * cold + sig_f(ig) * tanh_f(gg);
                float hn = sig_f(og) * tanh_f(cn);
                g_c[par ^ 1][b * H + j] = cn;
                g_h[par ^ 1][b * H + j] = hn;
            }
        }
    } else if (blk < 64) {
        // ---- out[t-1] GEMV: warp owns output unit j for all batches ----
        if (t == 0) return;
        for (int i = tid; i < B * H; i += 256) sbuf[i] = g_h[par][i];
        for (int i = tid; i < B * 2 * H; i += 256) sbuf[B * H + i] = g_ctx[i];
        __syncthreads();

        const int j = (blk - 32) * 8 + wid;
        float w[24];
        #pragma unroll
        for (int i = 0; i < 24; i++)
            w[i] = Wout[(size_t)j * (3 * H) + lane + i * 32];
        const float bo = bout[j];

        #pragma unroll 1
        for (int b = 0; b < B; b++) {
            const float* hb = sbuf + b * H;
            const float* cb = sbuf + B * H + b * 2 * H;
            float s = 0.f;
            #pragma unroll
            for (int i = 0; i < 8; i++) s += w[i] * hb[lane + i * 32];
            #pragma unroll
            for (int i = 0; i < 16; i++) s += w[8 + i] * cb[lane + i * 32];
            s = wreduce(s);
            if (lane == 0) o_out[((size_t)((t - 1) * B + b)) * H + j] = s + bo;
        }
    } else {
        // ---- p_gen[t-1] (warp per batch) + tail h_f/c_f copy ----
        if (t > 0) {
            const int b = (blk - 64) * 8 + wid;
            float s = 0.f;
            for (int k = lane; k < 4 * H + E; k += 32) {
                float cv;
                if (k < 2 * H) cv = g_ctx[b * 2 * H + k];
                else if (k < 3 * H) cv = g_h[par][b * H + k - 2 * H];
                else if (k < 4 * H) cv = g_c[par][b * H + k - 3 * H];
                else cv = g_x_all[((t - 1) * B + b) * E + k - 4 * H];
                s += cv * Wpg[k];
            }
            s = wreduce(s);
            if (lane == 0) o_pgen[(t - 1) * B + b] = sig_f(s + bpg[0]);
        }
        if (t == T_STEPS) {
            for (int i = (blk - 64) * 256 + tid; i < B * H; i += 512) {
                o_hf[i] = g_h[par][i];
                o_cf[i] = g_c[par][i];
            }
        }
    }
}

// ================= per-step kernel B: dec_feat =================
// grid = 32 blocks; warp owns j, batch loop; h_new/c_new staged in smem.
__global__ void __launch_bounds__(256)
k_dec(int t, const float* __restrict__ Ws_, const float* __restrict__ bs_) {
    __shared__ float sb[2 * B * H];   // 32 KB: h_new then c_new
    const int tid = threadIdx.x;
    const int lane = tid & 31, wid = tid >> 5;
    const int par = t & 1;

    for (int i = tid; i < B * H; i += 256) {
        sb[i] = g_h[par ^ 1][i];
        sb[B * H + i] = g_c[par ^ 1][i];
    }
    __syncthreads();

    const int j = blockIdx.x * 8 + wid;
    float w[16];
    #pragma unroll
    for (int i = 0; i < 16; i++)
        w[i] = Ws_[(size_t)j * (2 * H) + lane + i * 32];
    const float bsv = bs_[j];

    #pragma unroll 1
    for (int b = 0; b < B; b++) {
        const float* hb = sb + b * H;
        const float* cb = sb + B * H + b * H;
        float s = 0.f;
        #pragma unroll
        for (int i = 0; i < 8; i++) {
            s += w[i] * hb[lane + i * 32];
            s += w[8 + i] * cb[lane + i * 32];
        }
        s = wreduce(s);
        if (lane == 0) g_dec[b * H + j] = s + bsv;
    }
}

// ---------------- per-step kernel C: e[b,l] = sum_h v*tanh(enc_feat+dec) ----
// grid = 256 blocks x 256 threads = 2048 warps; 128 warps per b, 16 rows/warp.
__global__ void __launch_bounds__(256)
k_escore(int t, const float* __restrict__ v, float* __restrict__ o_attn) {
    const int tid = threadIdx.x;
    const int lane = tid & 31, wid = tid >> 5;
    const int gwarp = blockIdx.x * 8 + wid;
    const int b = gwarp >> 7;          // 128 warps per batch elem
    const int ww = gwarp & 127;

    const float4* d4 = (const float4*)(g_dec + b * H);
    const float4* v4 = (const float4*)v;
    float4 dfa = d4[lane * 2], dfb = d4[lane * 2 + 1];
    float4 sva = v4[lane * 2], svb = v4[lane * 2 + 1];

    float* e_out = o_attn + (size_t)t * B * L;
    for (int r = 0; r < 16; r++) {
        int l = ww * 16 + r;
        const float4* ef = (const float4*)(g_enc_feat + ((size_t)(b * L + l)) * H);
        float4 ea = ef[lane * 2], eb = ef[lane * 2 + 1];
        float s = sva.x * tanh_f(ea.x + dfa.x)
                + sva.y * tanh_f(ea.y + dfa.y)
                + sva.z * tanh_f(ea.z + dfa.z)
                + sva.w * tanh_f(ea.w + dfa.w)
                + svb.x * tanh_f(eb.x + dfb.x)
                + svb.y * tanh_f(eb.y + dfb.y)
                + svb.z * tanh_f(eb.z + dfb.z)
                + svb.w * tanh_f(eb.w + dfb.w);
        s = wreduce(s);
        if (lane == 0) e_out[b * L + l] = s;
    }
}

// ---------------- per-step kernel D: masked softmax in-place + zero ctx -----
__global__ void __launch_bounds__(256)
k_softmax(int t, const float* __restrict__ mask, float* __restrict__ o_attn) {
    __shared__ float scr[16];
    const int b = blockIdx.x, tid = threadIdx.x;
    const int lane = tid & 31, wid = tid >> 5;

    g_ctx[b * 2 * H + tid] = 0.f;
    g_ctx[b * 2 * H + H + tid] = 0.f;

    float* row = o_attn + ((size_t)(t * B + b)) * L;
    const float* mrow = mask + (size_t)b * L;

    float ev[8], mv[8];
    float mx = -3.4e38f;
    #pragma unroll
    for (int i = 0; i < 8; i++) {
        ev[i] = row[tid + i * 256];
        mv[i] = mrow[tid + i * 256];
        mx = fmaxf(mx, ev[i]);
    }
    #pragma unroll
    for (int off = 16; off; off >>= 1) mx = fmaxf(mx, __shfl_xor_sync(0xffffffffu, mx, off));
    if (lane == 0) scr[wid] = mx;
    __syncthreads();
    mx = scr[0];
    #pragma unroll
    for (int i = 1; i < 8; i++) mx = fmaxf(mx, scr[i]);

    float pv[8];
    float s = 0.f;
    #pragma unroll
    for (int i = 0; i < 8; i++) {
        pv[i] = __expf(ev[i] - mx) * mv[i];
        s += pv[i];
    }
    s = wreduce(s);
    if (lane == 0) scr[8 + wid] = s;
    __syncthreads();
    s = 0.f;
    #pragma unroll
    for (int i = 0; i < 8; i++) s += scr[8 + i];
    float inv = __fdividef(1.f, s);
    #pragma unroll
    for (int i = 0; i < 8; i++) row[tid + i * 256] = pv[i] * inv;
}

// ---------------- per-step kernel E: ctx = attn @ encoder_states -----------
__global__ void __launch_bounds__(256)
k_ctx(int t, const float* __restrict__ enc, const float* __restrict__ o_attn) {
    __shared__ float sa[128];
    const int b = blockIdx.x >> 4, ch = blockIdx.x & 15;
    const int l0 = ch * 128;
    const int tid = threadIdx.x;

    if (tid < 128) sa[tid] = o_attn[((size_t)(t * B + b)) * L + l0 + tid];
    __syncthreads();

    const int d = tid * 2;
    const float* es = enc + ((size_t)(b * L + l0)) * (2 * H) + d;
    float ax = 0.f, ay = 0.f;
    #pragma unroll 4
    for (int i = 0; i < 128; i++) {
        float a = sa[i];
        float2 s2 = *(const float2*)(es + (size_t)i * (2 * H));
        ax += a * s2.x;
        ay += a * s2.y;
    }
    atomicAdd(&g_ctx[b * 2 * H + d], ax);
    atomicAdd(&g_ctx[b * 2 * H + d + 1], ay);
}

// ---------------- host launcher ----------------
extern "C" void kernel_launch(void* const* d_in, const int* in_sizes, int n_in,
                              void* d_out, int out_size) {
    const float* dec_in = (const float*)d_in[0];
    const float* h0     = (const float*)d_in[1];
    const float* c0     = (const float*)d_in[2];
    const float* enc    = (const float*)d_in[3];
    const float* mask   = (const float*)d_in[4];
    const float* Wh     = (const float*)d_in[5];
    const float* bh     = (const float*)d_in[6];
    const float* Ws_    = (const float*)d_in[7];
    const float* bs_    = (const float*)d_in[8];
    const float* v      = (const float*)d_in[9];
    const float* Wx     = (const float*)d_in[10];
    const float* bx     = (const float*)d_in[11];
    const float* Wih    = (const float*)d_in[12];
    const float* bih    = (const float*)d_in[13];
    const float* Whh    = (const float*)d_in[14];
    const float* bhh    = (const float*)d_in[15];
    const float* Wpg    = (const float*)d_in[16];
    const float* bpg    = (const float*)d_in[17];
    const float* Wout   = (const float*)d_in[18];
    const float* bout   = (const float*)d_in[19];

    float* out = (float*)d_out;
    float* o_outputs = out;                                  // [T,B,H]
    float* o_hf = o_outputs + (size_t)T_STEPS * B * H;       // [B,H]
    float* o_cf = o_hf + B * H;                              // [B,H]
    float* o_attn = o_cf + B * H;                            // [T,B,L]
    float* o_pgen = o_attn + (size_t)T_STEPS * B * L;        // [T,B,1]

    k_pre0<<<512, 256>>>(Wh, h0, c0);
    k_pre_x<<<T_STEPS * B, 256>>>(dec_in, Wx, bx, Wih, bih, bhh);
    k_encfeat<<<dim3(4, 512), 256>>>(enc, bh);

    for (int t = 0; t < T_STEPS; t++) {
        k_A<<<66, 256>>>(t, Whh, Wout, bout, Wpg, bpg,
                         o_outputs, o_pgen, o_hf, o_cf);
        k_dec<<<32, 256>>>(t, Ws_, bs_);
        k_escore<<<256, 256>>>(t, v, o_attn);
        k_softmax<<<B, 256>>>(t, mask, o_attn);
        k_ctx<<<256, 256>>>(t, enc, o_attn);
    }
    // tail: epilogue for step 99 + h_f/c_f
    k_A<<<66, 256>>>(T_STEPS, Whh, Wout, bout, Wpg, bpg,
                     o_outputs, o_pgen, o_hf, o_cf);
}

// round 6
// speedup vs baseline: 3.3538x; 1.4003x over previous
#include <cuda_runtime.h>
#include <cuda_fp16.h>
#include <cstdint>

#define T_STEPS 100
#define B 16
#define E 128
#define H 256
#define L 2048

// ---------------- device scratch (static allocations only) ----------------
__device__ float g_enc_feat[B * L * H];                 // 33.5 MB fp32
__device__ __align__(16) __half g_enc_h[B * L * 2 * H]; // 33.5 MB fp16 mirror of enc_states
__device__ float g_WhT[512 * 256];
__device__ float g_x_all[T_STEPS * B * E];
__device__ float g_gi[T_STEPS * B * 4 * H];
__device__ float g_h[2][B * H];
__device__ float g_c[2][B * H];
__device__ float g_dec[B * H];
__device__ float g_ctx[B * 2 * H];
__device__ float g_e[B * L];                            // raw attention scores

// ---------------- fast math helpers ----------------
__device__ __forceinline__ float tanh_f(float x) {
    float e = __expf(2.f * x);
    return 1.f - __fdividef(2.f, e + 1.f);
}
__device__ __forceinline__ float sig_f(float x) {
    return __fdividef(1.f, 1.f + __expf(-x));
}
__device__ __forceinline__ float wreduce(float s) {
    #pragma unroll
    for (int off = 16; off; off >>= 1) s += __shfl_xor_sync(0xffffffffu, s, off);
    return s;
}
__device__ __forceinline__ float wmax(float s) {
    #pragma unroll
    for (int off = 16; off; off >>= 1) s = fmaxf(s, __shfl_xor_sync(0xffffffffu, s, off));
    return s;
}

// ---------------- pre-kernel 0: transpose Wh + init h/c ----------------
__global__ void k_pre0(const float* __restrict__ Wh,
                       const float* __restrict__ h0, const float* __restrict__ c0) {
    int i = blockIdx.x * 256 + threadIdx.x;
    int n = i & 255, k = i >> 8;
    g_WhT[i] = Wh[n * 512 + k];
    if (i < B * H) {
        g_h[0][i] = h0[i];
        g_c[0][i] = c0[i];
    }
}

// ---------------- pre-kernel 1: fp16 mirror of encoder_states --------------
__global__ void k_cvt(const float* __restrict__ enc) {
    size_t i = ((size_t)blockIdx.x * 256 + threadIdx.x) * 8;
    float4 a = *(const float4*)(enc + i);
    float4 b4 = *(const float4*)(enc + i + 4);
    __half2* o = (__half2*)(g_enc_h + i);
    o[0] = __floats2half2_rn(a.x, a.y);
    o[1] = __floats2half2_rn(a.z, a.w);
    o[2] = __floats2half2_rn(b4.x, b4.y);
    o[3] = __floats2half2_rn(b4.z, b4.w);
}

// ---------------- pre-kernel 2: x_all and gi -------------------------------
__global__ void k_pre_x(const float* __restrict__ dec_in,
                        const float* __restrict__ Wx, const float* __restrict__ bx,
                        const float* __restrict__ Wih, const float* __restrict__ bih,
                        const float* __restrict__ bhh) {
    __shared__ float s_in[E];
    __shared__ float s_x[E];
    int r = blockIdx.x;   // r = t*B + b
    int tid = threadIdx.x;
    if (tid < E) s_in[tid] = dec_in[r * E + tid];
    __syncthreads();
    if (tid < E) {
        int j = tid;
        const float* w = Wx + j * (2 * H + E);
        float s = bx[j];
        #pragma unroll 4
        for (int k = 0; k < E; k++) s += s_in[k] * w[k];
        s_x[j] = s;
        g_x_all[r * E + j] = s;
    }
    __syncthreads();
    for (int j = tid; j < 4 * H; j += 256) {
        const float* w = Wih + j * E;
        float s = bih[j] + bhh[j];
        #pragma unroll 4
        for (int k = 0; k < E; k++) s += s_x[k] * w[k];
        g_gi[r * 4 * H + j] = s;
    }
}

// ---------------- pre-kernel 3: enc_feat = enc_states @ Wh.T + bh ----------
__global__ void k_encfeat(const float* __restrict__ ES, const float* __restrict__ bh) {
    __shared__ float As[64][17];
    __shared__ float Bs[16][64];
    int m0 = blockIdx.y * 64;
    int n0 = blockIdx.x * 64;
    int tx = threadIdx.x & 15, ty = threadIdx.x >> 4;
    float acc[4][4] = {};
    for (int k0 = 0; k0 < 512; k0 += 16) {
        for (int i = threadIdx.x; i < 64 * 16; i += 256) {
            int m = i >> 4, k = i & 15;
            As[m][k] = ES[(size_t)(m0 + m) * 512 + k0 + k];
        }
        for (int i = threadIdx.x; i < 16 * 64; i += 256) {
            int k = i >> 6, n = i & 63;
            Bs[k][n] = g_WhT[(k0 + k) * 256 + n0 + n];
        }
        __syncthreads();
        #pragma unroll
        for (int kk = 0; kk < 16; kk++) {
            float a0 = As[ty * 4 + 0][kk];
            float a1 = As[ty * 4 + 1][kk];
            float a2 = As[ty * 4 + 2][kk];
            float a3 = As[ty * 4 + 3][kk];
            float4 b4 = *(const float4*)&Bs[kk][tx * 4];
            acc[0][0] += a0 * b4.x; acc[0][1] += a0 * b4.y; acc[0][2] += a0 * b4.z; acc[0][3] += a0 * b4.w;
            acc[1][0] += a1 * b4.x; acc[1][1] += a1 * b4.y; acc[1][2] += a1 * b4.z; acc[1][3] += a1 * b4.w;
            acc[2][0] += a2 * b4.x; acc[2][1] += a2 * b4.y; acc[2][2] += a2 * b4.z; acc[2][3] += a2 * b4.w;
            acc[3][0] += a3 * b4.x; acc[3][1] += a3 * b4.y; acc[3][2] += a3 * b4.z; acc[3][3] += a3 * b4.w;
        }
        __syncthreads();
    }
    #pragma unroll
    for (int i = 0; i < 4; i++) {
        int m = m0 + ty * 4 + i;
        #pragma unroll
        for (int j = 0; j < 4; j++) {
            int n = n0 + tx * 4 + j;
            g_enc_feat[(size_t)m * 256 + n] = acc[i][j] + bh[n];
        }
    }
}

// ================= per-step kernel A (130 blocks) =================
//   blocks   0-63 : LSTM gates — warp owns (unit j, 8 batches)
//   blocks  64-127: out[t-1] GEMV — warp owns (unit j, 8 batches)
//   blocks 128-129: p_gen[t-1]; at t==T_STEPS also h_f/c_f
__global__ void __launch_bounds__(256)
k_A(int t,
    const float* __restrict__ Whh,
    const float* __restrict__ Wout, const float* __restrict__ bout,
    const float* __restrict__ Wpg, const float* __restrict__ bpg,
    float* __restrict__ o_out, float* __restrict__ o_pgen,
    float* __restrict__ o_hf, float* __restrict__ o_cf) {
    __shared__ float sbuf[12288];   // 48 KB
    const int blk = blockIdx.x, tid = threadIdx.x;
    const int lane = tid & 31, wid = tid >> 5;
    const int par = t & 1;

    if (blk < 64) {
        // ---- LSTM gates ----
        if (t == T_STEPS) return;
        for (int i = tid; i < B * H; i += 256) sbuf[i] = g_h[par][i];
        __syncthreads();

        const int gw = blk * 8 + wid;        // [0,512)
        const int j = gw >> 1;
        const int half = gw & 1;             // batches half*8 .. +8

        float w[4][8];
        #pragma unroll
        for (int g = 0; g < 4; g++)
            #pragma unroll
            for (int i = 0; i < 8; i++)
                w[g][i] = Whh[(size_t)(g * H + j) * H + lane + i * 32];

        // lane i (<8) holds batch half*8+i scalars
        float cold = 0.f, gi0 = 0.f, gi1 = 0.f, gi2 = 0.f, gi3 = 0.f;
        if (lane < 8) {
            int bb = half * 8 + lane;
            cold = g_c[par][bb * H + j];
            const float* gi = g_gi + (size_t)(t * B + bb) * 4 * H;
            gi0 = gi[j]; gi1 = gi[H + j]; gi2 = gi[2 * H + j]; gi3 = gi[3 * H + j];
        }

        float acc[4];
        #pragma unroll 1
        for (int i8 = 0; i8 < 8; i8++) {
            int bb = half * 8 + i8;
            const float* hb = sbuf + bb * H;
            #pragma unroll
            for (int g = 0; g < 4; g++) {
                float s = 0.f;
                #pragma unroll
                for (int i = 0; i < 8; i++) s += w[g][i] * hb[lane + i * 32];
                acc[g] = wreduce(s);
            }
            if (lane == i8) {
                float ig = acc[0] + gi0;
                float fg = acc[1] + gi1;
                float gg = acc[2] + gi2;
                float og = acc[3] + gi3;
                float cn = sig_f(fg) * cold + sig_f(ig) * tanh_f(gg);
                float hn = sig_f(og) * tanh_f(cn);
                g_c[par ^ 1][bb * H + j] = cn;
                g_h[par ^ 1][bb * H + j] = hn;
            }
        }
    } else if (blk < 128) {
        // ---- out[t-1] GEMV ----
        if (t == 0) return;
        for (int i = tid; i < B * H; i += 256) sbuf[i] = g_h[par][i];
        for (int i = tid; i < B * 2 * H; i += 256) sbuf[B * H + i] = g_ctx[i];
        __syncthreads();

        const int gw = (blk - 64) * 8 + wid;
        const int j = gw >> 1;
        const int half = gw & 1;

        float w[24];
        #pragma unroll
        for (int i = 0; i < 24; i++)
            w[i] = Wout[(size_t)j * (3 * H) + lane + i * 32];
        const float bo = bout[j];

        #pragma unroll 1
        for (int i8 = 0; i8 < 8; i8++) {
            int bb = half * 8 + i8;
            const float* hb = sbuf + bb * H;
            const float* cb = sbuf + B * H + bb * 2 * H;
            float s = 0.f;
            #pragma unroll
            for (int i = 0; i < 8; i++) s += w[i] * hb[lane + i * 32];
            #pragma unroll
            for (int i = 0; i < 16; i++) s += w[8 + i] * cb[lane + i * 32];
            s = wreduce(s);
            if (lane == 0) o_out[((size_t)((t - 1) * B + bb)) * H + j] = s + bo;
        }
    } else {
        // ---- p_gen[t-1] + tail ----
        if (t > 0) {
            const int b = (blk - 128) * 8 + wid;
            float s = 0.f;
            for (int k = lane; k < 4 * H + E; k += 32) {
                float cv;
                if (k < 2 * H) cv = g_ctx[b * 2 * H + k];
                else if (k < 3 * H) cv = g_h[par][b * H + k - 2 * H];
                else if (k < 4 * H) cv = g_c[par][b * H + k - 3 * H];
                else cv = g_x_all[((t - 1) * B + b) * E + k - 4 * H];
                s += cv * Wpg[k];
            }
            s = wreduce(s);
            if (lane == 0) o_pgen[(t - 1) * B + b] = sig_f(s + bpg[0]);
        }
        if (t == T_STEPS) {
            for (int i = (blk - 128) * 256 + tid; i < B * H; i += 512) {
                o_hf[i] = g_h[par][i];
                o_cf[i] = g_c[par][i];
            }
        }
    }
}

// ================= per-step kernel B: dec_feat + zero ctx (64 blocks) ======
__global__ void __launch_bounds__(256)
k_dec(int t, const float* __restrict__ Ws_, const float* __restrict__ bs_) {
    __shared__ float sb[2 * B * H];   // 32 KB
    const int tid = threadIdx.x;
    const int lane = tid & 31, wid = tid >> 5;
    const int par = t & 1;

    if (blockIdx.x == 0) {
        #pragma unroll
        for (int i = 0; i < 32; i++) g_ctx[tid + i * 256] = 0.f;
    }
    for (int i = tid; i < B * H; i += 256) {
        sb[i] = g_h[par ^ 1][i];
        sb[B * H + i] = g_c[par ^ 1][i];
    }
    __syncthreads();

    const int gw = blockIdx.x * 8 + wid;   // [0,512)
    const int j = gw >> 1;
    const int half = gw & 1;

    float w[16];
    #pragma unroll
    for (int i = 0; i < 16; i++)
        w[i] = Ws_[(size_t)j * (2 * H) + lane + i * 32];
    const float bsv = bs_[j];

    #pragma unroll 1
    for (int i8 = 0; i8 < 8; i8++) {
        int bb = half * 8 + i8;
        const float* hb = sb + bb * H;
        const float* cb = sb + B * H + bb * H;
        float s = 0.f;
        #pragma unroll
        for (int i = 0; i < 8; i++) {
            s += w[i] * hb[lane + i * 32];
            s += w[8 + i] * cb[lane + i * 32];
        }
        s = wreduce(s);
        if (lane == 0) g_dec[bb * H + j] = s + bsv;
    }
}

// ---------------- per-step kernel C: raw e scores (256 blocks) -------------
__global__ void __launch_bounds__(256)
k_escore(int t, const float* __restrict__ v) {
    const int tid = threadIdx.x;
    const int lane = tid & 31, wid = tid >> 5;
    const int gwarp = blockIdx.x * 8 + wid;
    const int b = gwarp >> 7;
    const int ww = gwarp & 127;

    const float4* d4 = (const float4*)(g_dec + b * H);
    const float4* v4 = (const float4*)v;
    float4 dfa = d4[lane * 2], dfb = d4[lane * 2 + 1];
    float4 sva = v4[lane * 2], svb = v4[lane * 2 + 1];

    for (int r = 0; r < 16; r++) {
        int l = ww * 16 + r;
        const float4* ef = (const float4*)(g_enc_feat + ((size_t)(b * L + l)) * H);
        float4 ea = ef[lane * 2], eb = ef[lane * 2 + 1];
        float s = sva.x * tanh_f(ea.x + dfa.x)
                + sva.y * tanh_f(ea.y + dfa.y)
                + sva.z * tanh_f(ea.z + dfa.z)
                + sva.w * tanh_f(ea.w + dfa.w)
                + svb.x * tanh_f(eb.x + dfb.x)
                + svb.y * tanh_f(eb.y + dfb.y)
                + svb.z * tanh_f(eb.z + dfb.z)
                + svb.w * tanh_f(eb.w + dfb.w);
        s = wreduce(s);
        if (lane == 0) g_e[b * L + l] = s;
    }
}

// ---------------- per-step kernel D: softmax (redundant) + ctx (256 blocks)-
// block = b*16 + ch; each block re-reduces the full e row (max+sum), then
// normalizes its 128-chunk, writes o_attn, and accumulates ctx via atomics.
__global__ void __launch_bounds__(256)
k_ctxsm(int t, const float* __restrict__ mask, float* __restrict__ o_attn) {
    __shared__ float red[16];
    __shared__ float sa[128];
    const int b = blockIdx.x >> 4, ch = blockIdx.x & 15;
    const int l0 = ch * 128;
    const int tid = threadIdx.x;
    const int lane = tid & 31, wid = tid >> 5;

    const float* e_row = g_e + b * L;
    const float* mrow = mask + (size_t)b * L;

    // full-row max
    float ev[8];
    float mx = -3.4e38f;
    #pragma unroll
    for (int i = 0; i < 8; i++) {
        ev[i] = e_row[tid + i * 256];
        mx = fmaxf(mx, ev[i]);
    }
    mx = wmax(mx);
    if (lane == 0) red[wid] = mx;
    __syncthreads();
    mx = red[0];
    #pragma unroll
    for (int i = 1; i < 8; i++) mx = fmaxf(mx, red[i]);

    // full-row masked sum
    float s = 0.f;
    #pragma unroll
    for (int i = 0; i < 8; i++)
        s += __expf(ev[i] - mx) * mrow[tid + i * 256];
    s = wreduce(s);
    if (lane == 0) red[8 + wid] = s;
    __syncthreads();
    s = 0.f;
    #pragma unroll
    for (int i = 0; i < 8; i++) s += red[8 + i];
    float inv = __fdividef(1.f, s);

    // normalize own 128-chunk, write attn output + smem
    if (tid < 128) {
        float p = __expf(e_row[l0 + tid] - mx) * mrow[l0 + tid] * inv;
        sa[tid] = p;
        o_attn[((size_t)(t * B + b)) * L + l0 + tid] = p;
    }
    __syncthreads();

    // ctx partial: thread handles dims (2*tid, 2*tid+1) via half2
    const __half2* es = (const __half2*)(g_enc_h + ((size_t)(b * L + l0)) * (2 * H)) + tid;
    float ax = 0.f, ay = 0.f;
    #pragma unroll 4
    for (int i = 0; i < 128; i++) {
        float a = sa[i];
        float2 f = __half22float2(es[(size_t)i * 256]);
        ax += a * f.x;
        ay += a * f.y;
    }
    atomicAdd(&g_ctx[b * 2 * H + tid * 2], ax);
    atomicAdd(&g_ctx[b * 2 * H + tid * 2 + 1], ay);
}

// ---------------- host launcher ----------------
extern "C" void kernel_launch(void* const* d_in, const int* in_sizes, int n_in,
                              void* d_out, int out_size) {
    const float* dec_in = (const float*)d_in[0];
    const float* h0     = (const float*)d_in[1];
    const float* c0     = (const float*)d_in[2];
    const float* enc    = (const float*)d_in[3];
    const float* mask   = (const float*)d_in[4];
    const float* Wh     = (const float*)d_in[5];
    const float* bh     = (const float*)d_in[6];
    const float* Ws_    = (const float*)d_in[7];
    const float* bs_    = (const float*)d_in[8];
    const float* v      = (const float*)d_in[9];
    const float* Wx     = (const float*)d_in[10];
    const float* bx     = (const float*)d_in[11];
    const float* Wih    = (const float*)d_in[12];
    const float* bih    = (const float*)d_in[13];
    const float* Whh    = (const float*)d_in[14];
    const float* bhh    = (const float*)d_in[15];
    const float* Wpg    = (const float*)d_in[16];
    const float* bpg    = (const float*)d_in[17];
    const float* Wout   = (const float*)d_in[18];
    const float* bout   = (const float*)d_in[19];

    float* out = (float*)d_out;
    float* o_outputs = out;                                  // [T,B,H]
    float* o_hf = o_outputs + (size_t)T_STEPS * B * H;       // [B,H]
    float* o_cf = o_hf + B * H;                              // [B,H]
    float* o_attn = o_cf + B * H;                            // [T,B,L]
    float* o_pgen = o_attn + (size_t)T_STEPS * B * L;        // [T,B,1]

    k_pre0<<<512, 256>>>(Wh, h0, c0);
    k_cvt<<<8192, 256>>>(enc);
    k_pre_x<<<T_STEPS * B, 256>>>(dec_in, Wx, bx, Wih, bih, bhh);
    k_encfeat<<<dim3(4, 512), 256>>>(enc, bh);

    for (int t = 0; t < T_STEPS; t++) {
        k_A<<<130, 256>>>(t, Whh, Wout, bout, Wpg, bpg,
                          o_outputs, o_pgen, o_hf, o_cf);
        k_dec<<<64, 256>>>(t, Ws_, bs_);
        k_escore<<<256, 256>>>(t, v);
        k_ctxsm<<<256, 256>>>(t, mask, o_attn);
    }
    // tail: epilogue for step 99 + h_f/c_f
    k_A<<<130, 256>>>(T_STEPS, Whh, Wout, bout, Wpg, bpg,
                      o_outputs, o_pgen, o_hf, o_cf);
}

// round 7
// speedup vs baseline: 5.8919x; 1.7568x over previous
#include <cuda_runtime.h>
#include <cstdint>

#define T_STEPS 100
#define B 16
#define E 128
#define H 256
#define L 2048

// ---------------- device scratch (static allocations only) ----------------
__device__ float g_enc_feat[B * L * H];                 // 33.5 MB
__device__ float g_WhT[512 * 256];
__device__ float g_WsT[512 * 256];
__device__ float g_WoutT[768 * 256];
__device__ float g_x_all[T_STEPS * B * E];
__device__ float g_gi[T_STEPS * B * 4 * H];
__device__ float g_h_all[(T_STEPS + 1) * B * H];        // h after step t at index t
__device__ float g_c_all[(T_STEPS + 1) * B * H];
__device__ float g_dec_all[T_STEPS * B * H];            // dec_feat(t)
__device__ float g_ctx_all[T_STEPS * B * 2 * H];        // ctx(t)
__device__ float g_e_tr[B * L * 128];                   // e transposed [b][l][t(pad128)]

// ---------------- fast math helpers ----------------
__device__ __forceinline__ float tanh_f(float x) {
    float e = __expf(2.f * x);
    return 1.f - __fdividef(2.f, e + 1.f);
}
__device__ __forceinline__ float sig_f(float x) {
    return __fdividef(1.f, 1.f + __expf(-x));
}
__device__ __forceinline__ float wreduce(float s) {
    #pragma unroll
    for (int off = 16; off; off >>= 1) s += __shfl_xor_sync(0xffffffffu, s, off);
    return s;
}
__device__ __forceinline__ float wmax(float s) {
    #pragma unroll
    for (int off = 16; off; off >>= 1) s = fmaxf(s, __shfl_xor_sync(0xffffffffu, s, off));
    return s;
}
// packed f32x2 helpers (Blackwell)
__device__ __forceinline__ unsigned long long pack2(float x, float y) {
    unsigned long long r;
    asm("mov.b64 %0, {%1, %2};" : "=l"(r) : "f"(x), "f"(y));
    return r;
}
__device__ __forceinline__ void fma2(unsigned long long& d, unsigned long long a, unsigned long long b) {
    asm("fma.rn.f32x2 %0, %1, %2, %3;" : "=l"(d) : "l"(a), "l"(b), "l"(d));
}
__device__ __forceinline__ float2 unpack2(unsigned long long v) {
    float2 f;
    asm("mov.b64 {%0, %1}, %2;" : "=f"(f.x), "=f"(f.y) : "l"(v));
    return f;
}

// ---------------- transpose: dst[k][j] = src[j][k], j<256, k<C ----------
__global__ void k_tr(const float* __restrict__ src, float* __restrict__ dst, int C) {
    int i = blockIdx.x * 256 + threadIdx.x;   // i = k*256 + j
    int j = i & 255, k = i >> 8;
    dst[i] = src[j * C + k];
}

// ---------------- init h_all[0], c_all[0] ----------------
__global__ void k_init(const float* __restrict__ h0, const float* __restrict__ c0) {
    int i = blockIdx.x * 256 + threadIdx.x;
    g_h_all[i] = h0[i];
    g_c_all[i] = c0[i];
}

// ---------------- x_all and gi ----------------
__global__ void k_pre_x(const float* __restrict__ dec_in,
                        const float* __restrict__ Wx, const float* __restrict__ bx,
                        const float* __restrict__ Wih, const float* __restrict__ bih,
                        const float* __restrict__ bhh) {
    __shared__ float s_in[E];
    __shared__ float s_x[E];
    int r = blockIdx.x;   // r = t*B + b
    int tid = threadIdx.x;
    if (tid < E) s_in[tid] = dec_in[r * E + tid];
    __syncthreads();
    if (tid < E) {
        int j = tid;
        const float* w = Wx + j * (2 * H + E);
        float s = bx[j];
        #pragma unroll 4
        for (int k = 0; k < E; k++) s += s_in[k] * w[k];
        s_x[j] = s;
        g_x_all[r * E + j] = s;
    }
    __syncthreads();
    for (int j = tid; j < 4 * H; j += 256) {
        const float* w = Wih + j * E;
        float s = bih[j] + bhh[j];
        #pragma unroll 4
        for (int k = 0; k < E; k++) s += s_x[k] * w[k];
        g_gi[r * 4 * H + j] = s;
    }
}

// ---------------- enc_feat GEMM: 128x64 tile, f32x2, M-pairs ----------------
__global__ void __launch_bounds__(256)
k_encfeat2(const float* __restrict__ ES, const float* __restrict__ bh) {
    __shared__ __align__(16) float Ast[16][132];
    __shared__ __align__(16) float Bs[16][64];
    const int tid = threadIdx.x;
    const int m0 = blockIdx.y * 128;
    const int n0 = blockIdx.x * 64;
    const int tx = tid & 15, ty = tid >> 4;
    unsigned long long acc[4][4];
    #pragma unroll
    for (int p = 0; p < 4; p++)
        #pragma unroll
        for (int n = 0; n < 4; n++) acc[p][n] = 0ull;

    for (int k0 = 0; k0 < 512; k0 += 16) {
        __syncthreads();
        #pragma unroll
        for (int u = 0; u < 2; u++) {
            int idx = u * 256 + tid;
            int row = idx >> 2, q = idx & 3;
            float4 f = *(const float4*)(ES + (size_t)(m0 + row) * 512 + k0 + q * 4);
            Ast[q * 4 + 0][row] = f.x;
            Ast[q * 4 + 1][row] = f.y;
            Ast[q * 4 + 2][row] = f.z;
            Ast[q * 4 + 3][row] = f.w;
        }
        {
            int kk = tid >> 4, n4 = (tid & 15) * 4;
            *(float4*)&Bs[kk][n4] = *(const float4*)(g_WhT + (size_t)(k0 + kk) * 256 + n0 + n4);
        }
        __syncthreads();
        #pragma unroll
        for (int kk = 0; kk < 16; kk++) {
            unsigned long long a2[4];
            #pragma unroll
            for (int p = 0; p < 4; p++)
                a2[p] = *(const unsigned long long*)&Ast[kk][ty * 8 + p * 2];
            float4 b4 = *(const float4*)&Bs[kk][tx * 4];
            unsigned long long bb[4];
            bb[0] = pack2(b4.x, b4.x); bb[1] = pack2(b4.y, b4.y);
            bb[2] = pack2(b4.z, b4.z); bb[3] = pack2(b4.w, b4.w);
            #pragma unroll
            for (int p = 0; p < 4; p++)
                #pragma unroll
                for (int n = 0; n < 4; n++)
                    fma2(acc[p][n], a2[p], bb[n]);
        }
    }
    #pragma unroll
    for (int p = 0; p < 4; p++) {
        int m = m0 + ty * 8 + p * 2;
        #pragma unroll
        for (int n = 0; n < 4; n++) {
            float2 f = unpack2(acc[p][n]);
            int col = n0 + tx * 4 + n;
            float bv = bh[col];
            g_enc_feat[(size_t)m * 256 + col] = f.x + bv;
            g_enc_feat[(size_t)(m + 1) * 256 + col] = f.y + bv;
        }
    }
}

// ---------------- gates step (64 blocks), h_all[t] -> h_all[t+1] ----------
__global__ void __launch_bounds__(256)
k_gates(int t, const float* __restrict__ Whh) {
    __shared__ float sh[B * H];   // 16 KB
    const int tid = threadIdx.x;
    const int lane = tid & 31, wid = tid >> 5;

    const float* hprev = g_h_all + (size_t)t * B * H;
    for (int i = tid; i < B * H; i += 256) sh[i] = hprev[i];
    __syncthreads();

    const int gw = blockIdx.x * 8 + wid;   // [0,512)
    const int j = gw >> 1;
    const int half = gw & 1;

    float w[4][8];
    #pragma unroll
    for (int g = 0; g < 4; g++)
        #pragma unroll
        for (int i = 0; i < 8; i++)
            w[g][i] = Whh[(size_t)(g * H + j) * H + lane + i * 32];

    float cold = 0.f, gi0 = 0.f, gi1 = 0.f, gi2 = 0.f, gi3 = 0.f;
    if (lane < 8) {
        int bb = half * 8 + lane;
        cold = g_c_all[(size_t)t * B * H + bb * H + j];
        const float* gi = g_gi + (size_t)(t * B + bb) * 4 * H;
        gi0 = gi[j]; gi1 = gi[H + j]; gi2 = gi[2 * H + j]; gi3 = gi[3 * H + j];
    }

    float acc[4];
    #pragma unroll 1
    for (int i8 = 0; i8 < 8; i8++) {
        int bb = half * 8 + i8;
        const float* hb = sh + bb * H;
        #pragma unroll
        for (int g = 0; g < 4; g++) {
            float s = 0.f;
            #pragma unroll
            for (int i = 0; i < 8; i++) s += w[g][i] * hb[lane + i * 32];
            acc[g] = wreduce(s);
        }
        if (lane == i8) {
            float ig = acc[0] + gi0;
            float fg = acc[1] + gi1;
            float gg = acc[2] + gi2;
            float og = acc[3] + gi3;
            float cn = sig_f(fg) * cold + sig_f(ig) * tanh_f(gg);
            float hn = sig_f(og) * tanh_f(cn);
            g_c_all[(size_t)(t + 1) * B * H + bb * H + j] = cn;
            g_h_all[(size_t)(t + 1) * B * H + bb * H + j] = hn;
        }
    }
}

// ---------------- dec_feat batched GEMM: [1600,512]x[512,256] --------------
__global__ void __launch_bounds__(256)
k_dec_gemm(const float* __restrict__ bs_) {
    __shared__ float As[64][17];
    __shared__ float Bs[16][64];
    const int m0 = blockIdx.y * 64;
    const int n0 = blockIdx.x * 64;
    const int tid = threadIdx.x;
    const int tx = tid & 15, ty = tid >> 4;
    float acc[4][4] = {};
    for (int k0 = 0; k0 < 512; k0 += 16) {
        for (int i = tid; i < 64 * 16; i += 256) {
            int m = i >> 4, k = i & 15;
            int r = m0 + m;
            int t = r >> 4, bb = r & 15;
            int kk = k0 + k;
            float v = (kk < 256)
                ? g_h_all[(size_t)(t + 1) * B * H + bb * H + kk]
                : g_c_all[(size_t)(t + 1) * B * H + bb * H + kk - 256];
            As[m][k] = v;
        }
        for (int i = tid; i < 16 * 64; i += 256) {
            int k = i >> 6, n = i & 63;
            Bs[k][n] = g_WsT[(size_t)(k0 + k) * 256 + n0 + n];
        }
        __syncthreads();
        #pragma unroll
        for (int kk = 0; kk < 16; kk++) {
            float a0 = As[ty * 4 + 0][kk];
            float a1 = As[ty * 4 + 1][kk];
            float a2 = As[ty * 4 + 2][kk];
            float a3 = As[ty * 4 + 3][kk];
            float4 b4 = *(const float4*)&Bs[kk][tx * 4];
            acc[0][0] += a0 * b4.x; acc[0][1] += a0 * b4.y; acc[0][2] += a0 * b4.z; acc[0][3] += a0 * b4.w;
            acc[1][0] += a1 * b4.x; acc[1][1] += a1 * b4.y; acc[1][2] += a1 * b4.z; acc[1][3] += a1 * b4.w;
            acc[2][0] += a2 * b4.x; acc[2][1] += a2 * b4.y; acc[2][2] += a2 * b4.z; acc[2][3] += a2 * b4.w;
            acc[3][0] += a3 * b4.x; acc[3][1] += a3 * b4.y; acc[3][2] += a3 * b4.z; acc[3][3] += a3 * b4.w;
        }
        __syncthreads();
    }
    #pragma unroll
    for (int i = 0; i < 4; i++) {
        int r = m0 + ty * 4 + i;
        #pragma unroll
        for (int j = 0; j < 4; j++) {
            int n = n0 + tx * 4 + j;
            g_dec_all[(size_t)r * 256 + n] = acc[i][j] + bs_[n];
        }
    }
}

// ---------------- batched e-scores: warp per (b,l), loop t -----------------
__global__ void __launch_bounds__(256)
k_escore_all(const float* __restrict__ v) {
    const int tid = threadIdx.x;
    const int lane = tid & 31, wid = tid >> 5;
    const int gwarp = blockIdx.x * 8 + wid;     // [0, 32768)
    const int b = gwarp >> 11;                  // 2048 warps per b
    const int l = gwarp & 2047;

    const float4* ef4 = (const float4*)(g_enc_feat + ((size_t)(b * L + l)) * H);
    const float4* v4 = (const float4*)v;
    float4 ea = ef4[lane * 2], eb = ef4[lane * 2 + 1];
    float4 sva = v4[lane * 2], svb = v4[lane * 2 + 1];

    float* eout = g_e_tr + ((size_t)(b * L + l)) * 128;

    #pragma unroll 1
    for (int c = 0; c < 4; c++) {
        float ereg = 0.f;
        int tmax = T_STEPS - c * 32;
        if (tmax > 32) tmax = 32;
        #pragma unroll 1
        for (int tt = 0; tt < tmax; tt++) {
            int t = c * 32 + tt;
            const float4* d4 = (const float4*)(g_dec_all + (size_t)(t * B + b) * H);
            float4 dfa = d4[lane * 2], dfb = d4[lane * 2 + 1];
            float s = sva.x * tanh_f(ea.x + dfa.x)
                    + sva.y * tanh_f(ea.y + dfa.y)
                    + sva.z * tanh_f(ea.z + dfa.z)
                    + sva.w * tanh_f(ea.w + dfa.w)
                    + svb.x * tanh_f(eb.x + dfb.x)
                    + svb.y * tanh_f(eb.y + dfb.y)
                    + svb.z * tanh_f(eb.z + dfb.z)
                    + svb.w * tanh_f(eb.w + dfb.w);
            s = wreduce(s);
            if (tt == lane) ereg = s;
        }
        if (c * 32 + lane < T_STEPS) eout[c * 32 + lane] = ereg;
    }
}

// ---------------- batched softmax: block per (t,b) -------------------------
__global__ void __launch_bounds__(256)
k_softmax_all(const float* __restrict__ mask, float* __restrict__ o_attn) {
    __shared__ float red[16];
    const int r = blockIdx.x;         // r = t*B + b
    const int t = r >> 4, b = r & 15;
    const int tid = threadIdx.x;
    const int lane = tid & 31, wid = tid >> 5;

    const float* mrow = mask + (size_t)b * L;

    float ev[8], mv[8];
    float mx = -3.4e38f;
    #pragma unroll
    for (int i = 0; i < 8; i++) {
        int l = tid + i * 256;
        ev[i] = g_e_tr[((size_t)(b * L + l)) * 128 + t];
        mv[i] = mrow[l];
        mx = fmaxf(mx, ev[i]);
    }
    mx = wmax(mx);
    if (lane == 0) red[wid] = mx;
    __syncthreads();
    mx = red[0];
    #pragma unroll
    for (int i = 1; i < 8; i++) mx = fmaxf(mx, red[i]);

    float pv[8];
    float s = 0.f;
    #pragma unroll
    for (int i = 0; i < 8; i++) {
        pv[i] = __expf(ev[i] - mx) * mv[i];
        s += pv[i];
    }
    s = wreduce(s);
    if (lane == 0) red[8 + wid] = s;
    __syncthreads();
    s = 0.f;
    #pragma unroll
    for (int i = 0; i < 8; i++) s += red[8 + i];
    float inv = __fdividef(1.f, s);
    #pragma unroll
    for (int i = 0; i < 8; i++)
        o_attn[(size_t)r * L + tid + i * 256] = pv[i] * inv;
}

// ---------------- ctx batched GEMM per b: [128(t),2048]x[2048,512] ---------
__global__ void __launch_bounds__(256)
k_ctx_gemm(const float* __restrict__ enc, const float* __restrict__ o_attn) {
    __shared__ __align__(16) float Ast[16][132];
    __shared__ __align__(16) float Bs[16][64];
    const int tid = threadIdx.x;
    const int b = blockIdx.y;
    const int n0 = blockIdx.x * 64;
    const int tx = tid & 15, ty = tid >> 4;
    unsigned long long acc[4][4];
    #pragma unroll
    for (int p = 0; p < 4; p++)
        #pragma unroll
        for (int n = 0; n < 4; n++) acc[p][n] = 0ull;

    for (int k0 = 0; k0 < L; k0 += 16) {
        __syncthreads();
        #pragma unroll
        for (int u = 0; u < 2; u++) {
            int idx = u * 256 + tid;
            int row = idx >> 2, q = idx & 3;   // row = t (0..127)
            float4 f = make_float4(0.f, 0.f, 0.f, 0.f);
            if (row < T_STEPS)
                f = *(const float4*)(o_attn + ((size_t)(row * B + b)) * L + k0 + q * 4);
            Ast[q * 4 + 0][row] = f.x;
            Ast[q * 4 + 1][row] = f.y;
            Ast[q * 4 + 2][row] = f.z;
            Ast[q * 4 + 3][row] = f.w;
        }
        {
            int kk = tid >> 4, n4 = (tid & 15) * 4;
            *(float4*)&Bs[kk][n4] =
                *(const float4*)(enc + ((size_t)(b * L + k0 + kk)) * (2 * H) + n0 + n4);
        }
        __syncthreads();
        #pragma unroll
        for (int kk = 0; kk < 16; kk++) {
            unsigned long long a2[4];
            #pragma unroll
            for (int p = 0; p < 4; p++)
                a2[p] = *(const unsigned long long*)&Ast[kk][ty * 8 + p * 2];
            float4 b4 = *(const float4*)&Bs[kk][tx * 4];
            unsigned long long bb[4];
            bb[0] = pack2(b4.x, b4.x); bb[1] = pack2(b4.y, b4.y);
            bb[2] = pack2(b4.z, b4.z); bb[3] = pack2(b4.w, b4.w);
            #pragma unroll
            for (int p = 0; p < 4; p++)
                #pragma unroll
                for (int n = 0; n < 4; n++)
                    fma2(acc[p][n], a2[p], bb[n]);
        }
    }
    #pragma unroll
    for (int p = 0; p < 4; p++) {
        int t = ty * 8 + p * 2;
        #pragma unroll
        for (int n = 0; n < 4; n++) {
            float2 f = unpack2(acc[p][n]);
            int col = n0 + tx * 4 + n;
            if (t < T_STEPS)
                g_ctx_all[(size_t)(t * B + b) * (2 * H) + col] = f.x;
            if (t + 1 < T_STEPS)
                g_ctx_all[(size_t)((t + 1) * B + b) * (2 * H) + col] = f.y;
        }
    }
}

// ---------------- out batched GEMM: [1600,768]x[768,256] -------------------
__global__ void __launch_bounds__(256)
k_out_gemm(const float* __restrict__ bout, float* __restrict__ o_out) {
    __shared__ float As[64][17];
    __shared__ float Bs[16][64];
    const int m0 = blockIdx.y * 64;
    const int n0 = blockIdx.x * 64;
    const int tid = threadIdx.x;
    const int tx = tid & 15, ty = tid >> 4;
    float acc[4][4] = {};
    for (int k0 = 0; k0 < 768; k0 += 16) {
        for (int i = tid; i < 64 * 16; i += 256) {
            int m = i >> 4, k = i & 15;
            int r = m0 + m;
            int t = r >> 4, bb = r & 15;
            int kk = k0 + k;
            float v = (kk < 256)
                ? g_h_all[(size_t)(t + 1) * B * H + bb * H + kk]
                : g_ctx_all[(size_t)r * 512 + kk - 256];
            As[m][k] = v;
        }
        for (int i = tid; i < 16 * 64; i += 256) {
            int k = i >> 6, n = i & 63;
            Bs[k][n] = g_WoutT[(size_t)(k0 + k) * 256 + n0 + n];
        }
        __syncthreads();
        #pragma unroll
        for (int kk = 0; kk < 16; kk++) {
            float a0 = As[ty * 4 + 0][kk];
            float a1 = As[ty * 4 + 1][kk];
            float a2 = As[ty * 4 + 2][kk];
            float a3 = As[ty * 4 + 3][kk];
            float4 b4 = *(const float4*)&Bs[kk][tx * 4];
            acc[0][0] += a0 * b4.x; acc[0][1] += a0 * b4.y; acc[0][2] += a0 * b4.z; acc[0][3] += a0 * b4.w;
            acc[1][0] += a1 * b4.x; acc[1][1] += a1 * b4.y; acc[1][2] += a1 * b4.z; acc[1][3] += a1 * b4.w;
            acc[2][0] += a2 * b4.x; acc[2][1] += a2 * b4.y; acc[2][2] += a2 * b4.z; acc[2][3] += a2 * b4.w;
            acc[3][0] += a3 * b4.x; acc[3][1] += a3 * b4.y; acc[3][2] += a3 * b4.z; acc[3][3] += a3 * b4.w;
        }
        __syncthreads();
    }
    #pragma unroll
    for (int i = 0; i < 4; i++) {
        int r = m0 + ty * 4 + i;
        #pragma unroll
        for (int j = 0; j < 4; j++) {
            int n = n0 + tx * 4 + j;
            o_out[(size_t)r * 256 + n] = acc[i][j] + bout[n];
        }
    }
}

// ---------------- p_gen batched + h_f/c_f ----------------------------------
__global__ void __launch_bounds__(256)
k_pgen(const float* __restrict__ Wpg, const float* __restrict__ bpg,
       float* __restrict__ o_pgen, float* __restrict__ o_hf, float* __restrict__ o_cf) {
    const int tid = threadIdx.x;
    const int lane = tid & 31, wid = tid >> 5;
    const int blk = blockIdx.x;

    if (blk < 200) {
        const int r = blk * 8 + wid;     // [0, 1600)
        const int t = r >> 4, bb = r & 15;
        float s = 0.f;
        for (int k = lane; k < 4 * H + E; k += 32) {
            float cv;
            if (k < 2 * H) cv = g_ctx_all[(size_t)r * 512 + k];
            else if (k < 3 * H) cv = g_h_all[(size_t)(t + 1) * B * H + bb * H + k - 2 * H];
            else if (k < 4 * H) cv = g_c_all[(size_t)(t + 1) * B * H + bb * H + k - 3 * H];
            else cv = g_x_all[(size_t)r * E + k - 4 * H];
            s += cv * Wpg[k];
        }
        s = wreduce(s);
        if (lane == 0) o_pgen[r] = sig_f(s + bpg[0]);
    } else {
        for (int i = (blk - 200) * 256 + tid; i < B * H; i += 512) {
            o_hf[i] = g_h_all[(size_t)T_STEPS * B * H + i];
            o_cf[i] = g_c_all[(size_t)T_STEPS * B * H + i];
        }
    }
}

// ---------------- host launcher ----------------
extern "C" void kernel_launch(void* const* d_in, const int* in_sizes, int n_in,
                              void* d_out, int out_size) {
    const float* dec_in = (const float*)d_in[0];
    const float* h0     = (const float*)d_in[1];
    const float* c0     = (const float*)d_in[2];
    const float* enc    = (const float*)d_in[3];
    const float* mask   = (const float*)d_in[4];
    const float* Wh     = (const float*)d_in[5];
    const float* bh     = (const float*)d_in[6];
    const float* Ws_    = (const float*)d_in[7];
    const float* bs_    = (const float*)d_in[8];
    const float* v      = (const float*)d_in[9];
    const float* Wx     = (const float*)d_in[10];
    const float* bx     = (const float*)d_in[11];
    const float* Wih    = (const float*)d_in[12];
    const float* bih    = (const float*)d_in[13];
    const float* Whh    = (const float*)d_in[14];
    const float* bhh    = (const float*)d_in[15];
    const float* Wpg    = (const float*)d_in[16];
    const float* bpg    = (const float*)d_in[17];
    const float* Wout   = (const float*)d_in[18];
    const float* bout   = (const float*)d_in[19];

    float* out = (float*)d_out;
    float* o_outputs = out;                                  // [T,B,H]
    float* o_hf = o_outputs + (size_t)T_STEPS * B * H;       // [B,H]
    float* o_cf = o_hf + B * H;                              // [B,H]
    float* o_attn = o_cf + B * H;                            // [T,B,L]
    float* o_pgen = o_attn + (size_t)T_STEPS * B * L;        // [T,B,1]

    // resolve device symbol addresses for kernels that take them as args
    float* d_WhT = nullptr;   cudaGetSymbolAddress((void**)&d_WhT, g_WhT);
    float* d_WsT = nullptr;   cudaGetSymbolAddress((void**)&d_WsT, g_WsT);
    float* d_WoutT = nullptr; cudaGetSymbolAddress((void**)&d_WoutT, g_WoutT);

    k_tr<<<512, 256>>>(Wh, d_WhT, 512);
    k_tr<<<512, 256>>>(Ws_, d_WsT, 512);
    k_tr<<<768, 256>>>(Wout, d_WoutT, 768);
    k_init<<<16, 256>>>(h0, c0);
    k_pre_x<<<T_STEPS * B, 256>>>(dec_in, Wx, bx, Wih, bih, bhh);
    k_encfeat2<<<dim3(4, 256), 256>>>(enc, bh);

    for (int t = 0; t < T_STEPS; t++)
        k_gates<<<64, 256>>>(t, Whh);

    k_dec_gemm<<<dim3(4, 25), 256>>>(bs_);
    k_escore_all<<<4096, 256>>>(v);
    k_softmax_all<<<1600, 256>>>(mask, o_attn);
    k_ctx_gemm<<<dim3(8, 16), 256>>>(enc, o_attn);
    k_out_gemm<<<dim3(4, 25), 256>>>(bout, o_outputs);
    k_pgen<<<202, 256>>>(Wpg, bpg, o_pgen, o_hf, o_cf);
}

// round 8
// speedup vs baseline: 6.8312x; 1.1594x over previous
#include <cuda_runtime.h>
#include <cstdint>

#define T_STEPS 100
#define B 16
#define E 128
#define H 256
#define L 2048
#define CHAIN_BLOCKS 64

// ---------------- device scratch (static allocations only) ----------------
__device__ float g_enc_feat[B * L * H];                 // 33.5 MB
__device__ float g_WhT[512 * 256];
__device__ float g_WsT[512 * 256];
__device__ float g_WoutT[768 * 256];
__device__ float g_x_all[T_STEPS * B * E];
__device__ float g_gi[T_STEPS * B * 4 * H];
__device__ float g_h_all[(T_STEPS + 1) * B * H];        // h after step t at index t
__device__ float g_c_all[(T_STEPS + 1) * B * H];
__device__ float g_dec_all[T_STEPS * B * H];            // dec_feat(t)
__device__ float g_ctx_all[T_STEPS * B * 2 * H];        // ctx(t)
__device__ float g_e_tr[B * L * 128];                   // e transposed [b][l][t(pad128)]
__device__ unsigned g_barc;                             // chain barrier counter

// ---------------- fast math helpers ----------------
__device__ __forceinline__ float tanh_f(float x) {
    float e = __expf(2.f * x);
    return 1.f - __fdividef(2.f, e + 1.f);
}
__device__ __forceinline__ float sig_f(float x) {
    return __fdividef(1.f, 1.f + __expf(-x));
}
__device__ __forceinline__ float wreduce(float s) {
    #pragma unroll
    for (int off = 16; off; off >>= 1) s += __shfl_xor_sync(0xffffffffu, s, off);
    return s;
}
__device__ __forceinline__ float wmax(float s) {
    #pragma unroll
    for (int off = 16; off; off >>= 1) s = fmaxf(s, __shfl_xor_sync(0xffffffffu, s, off));
    return s;
}
// packed f32x2 helpers (Blackwell)
__device__ __forceinline__ unsigned long long pack2(float x, float y) {
    unsigned long long r;
    asm("mov.b64 %0, {%1, %2};" : "=l"(r) : "f"(x), "f"(y));
    return r;
}
__device__ __forceinline__ void fma2(unsigned long long& d, unsigned long long a, unsigned long long b) {
    asm("fma.rn.f32x2 %0, %1, %2, %3;" : "=l"(d) : "l"(a), "l"(b), "l"(d));
}
__device__ __forceinline__ float2 unpack2(unsigned long long v) {
    float2 f;
    asm("mov.b64 {%0, %1}, %2;" : "=f"(f.x), "=f"(f.y) : "l"(v));
    return f;
}

// ---------------- prep: transposes + h/c init + barrier reset --------------
// grid = 1808 blocks: [0,512) WhT, [512,1024) WsT, [1024,1792) WoutT,
//                     [1792,1808) init h/c
__global__ void k_prep(const float* __restrict__ Wh, const float* __restrict__ Ws_,
                       const float* __restrict__ Wout,
                       const float* __restrict__ h0, const float* __restrict__ c0) {
    int blk = blockIdx.x, tid = threadIdx.x;
    if (blk == 0 && tid == 0) g_barc = 0u;
    if (blk < 512) {
        int i = blk * 256 + tid;
        int j = i & 255, k = i >> 8;
        g_WhT[i] = Wh[j * 512 + k];
    } else if (blk < 1024) {
        int i = (blk - 512) * 256 + tid;
        int j = i & 255, k = i >> 8;
        g_WsT[i] = Ws_[j * 512 + k];
    } else if (blk < 1792) {
        int i = (blk - 1024) * 256 + tid;
        int j = i & 255, k = i >> 8;
        g_WoutT[i] = Wout[j * 768 + k];
    } else {
        int i = (blk - 1792) * 256 + tid;
        g_h_all[i] = h0[i];
        g_c_all[i] = c0[i];
    }
}

// ---------------- x_all and gi ----------------
__global__ void k_pre_x(const float* __restrict__ dec_in,
                        const float* __restrict__ Wx, const float* __restrict__ bx,
                        const float* __restrict__ Wih, const float* __restrict__ bih,
                        const float* __restrict__ bhh) {
    __shared__ float s_in[E];
    __shared__ float s_x[E];
    int r = blockIdx.x;   // r = t*B + b
    int tid = threadIdx.x;
    if (tid < E) s_in[tid] = dec_in[r * E + tid];
    __syncthreads();
    if (tid < E) {
        int j = tid;
        const float* w = Wx + j * (2 * H + E);
        float s = bx[j];
        #pragma unroll 4
        for (int k = 0; k < E; k++) s += s_in[k] * w[k];
        s_x[j] = s;
        g_x_all[r * E + j] = s;
    }
    __syncthreads();
    for (int j = tid; j < 4 * H; j += 256) {
        const float* w = Wih + j * E;
        float s = bih[j] + bhh[j];
        #pragma unroll 4
        for (int k = 0; k < E; k++) s += s_x[k] * w[k];
        g_gi[r * 4 * H + j] = s;
    }
}

// ---------------- enc_feat GEMM: 128x64 tile, f32x2, M-pairs ----------------
__global__ void __launch_bounds__(256)
k_encfeat2(const float* __restrict__ ES, const float* __restrict__ bh) {
    __shared__ __align__(16) float Ast[16][132];
    __shared__ __align__(16) float Bs[16][64];
    const int tid = threadIdx.x;
    const int m0 = blockIdx.y * 128;
    const int n0 = blockIdx.x * 64;
    const int tx = tid & 15, ty = tid >> 4;
    unsigned long long acc[4][4];
    #pragma unroll
    for (int p = 0; p < 4; p++)
        #pragma unroll
        for (int n = 0; n < 4; n++) acc[p][n] = 0ull;

    for (int k0 = 0; k0 < 512; k0 += 16) {
        __syncthreads();
        #pragma unroll
        for (int u = 0; u < 2; u++) {
            int idx = u * 256 + tid;
            int row = idx >> 2, q = idx & 3;
            float4 f = *(const float4*)(ES + (size_t)(m0 + row) * 512 + k0 + q * 4);
            Ast[q * 4 + 0][row] = f.x;
            Ast[q * 4 + 1][row] = f.y;
            Ast[q * 4 + 2][row] = f.z;
            Ast[q * 4 + 3][row] = f.w;
        }
        {
            int kk = tid >> 4, n4 = (tid & 15) * 4;
            *(float4*)&Bs[kk][n4] = *(const float4*)(g_WhT + (size_t)(k0 + kk) * 256 + n0 + n4);
        }
        __syncthreads();
        #pragma unroll
        for (int kk = 0; kk < 16; kk++) {
            unsigned long long a2[4];
            #pragma unroll
            for (int p = 0; p < 4; p++)
                a2[p] = *(const unsigned long long*)&Ast[kk][ty * 8 + p * 2];
            float4 b4 = *(const float4*)&Bs[kk][tx * 4];
            unsigned long long bb[4];
            bb[0] = pack2(b4.x, b4.x); bb[1] = pack2(b4.y, b4.y);
            bb[2] = pack2(b4.z, b4.z); bb[3] = pack2(b4.w, b4.w);
            #pragma unroll
            for (int p = 0; p < 4; p++)
                #pragma unroll
                for (int n = 0; n < 4; n++)
                    fma2(acc[p][n], a2[p], bb[n]);
        }
    }
    #pragma unroll
    for (int p = 0; p < 4; p++) {
        int m = m0 + ty * 8 + p * 2;
        #pragma unroll
        for (int n = 0; n < 4; n++) {
            float2 f = unpack2(acc[p][n]);
            int col = n0 + tx * 4 + n;
            float bv = bh[col];
            g_enc_feat[(size_t)m * 256 + col] = f.x + bv;
            g_enc_feat[(size_t)(m + 1) * 256 + col] = f.y + bv;
        }
    }
}

// ---------------- persistent LSTM chain: 64 blocks, 100 steps --------------
// warp gw = blk*8+wid owns (j = gw>>1, batch-half = gw&1). Weights + c in regs.
__global__ void __launch_bounds__(256)
k_chain(const float* __restrict__ Whh) {
    __shared__ float sh[B * H];   // 16 KB staged h(t)
    const int tid = threadIdx.x;
    const int lane = tid & 31, wid = tid >> 5;
    const int gw = blockIdx.x * 8 + wid;
    const int j = gw >> 1;
    const int half = gw & 1;

    // weights resident for the whole chain
    float w[4][8];
    #pragma unroll
    for (int g = 0; g < 4; g++)
        #pragma unroll
        for (int i = 0; i < 8; i++)
            w[g][i] = Whh[(size_t)(g * H + j) * H + lane + i * 32];

    // c resident: lane i8 (<8) holds c[half*8+i8][j]
    float creg = 0.f;
    if (lane < 8) creg = g_c_all[(half * 8 + lane) * H + j];

    for (int t = 0; t < T_STEPS; t++) {
        // stage h(t) — written by other blocks → __ldcg
        {
            const float* hsrc = g_h_all + (size_t)t * B * H;
            #pragma unroll
            for (int i = 0; i < 16; i++) sh[tid + i * 256] = __ldcg(hsrc + tid + i * 256);
        }
        __syncthreads();

        // gi for this step (L2-resident, written pre-chain)
        float gi0 = 0.f, gi1 = 0.f, gi2 = 0.f, gi3 = 0.f;
        if (lane < 8) {
            const float* gi = g_gi + (size_t)(t * B + half * 8 + lane) * 4 * H;
            gi0 = gi[j]; gi1 = gi[H + j]; gi2 = gi[2 * H + j]; gi3 = gi[3 * H + j];
        }

        float acc[4];
        #pragma unroll 1
        for (int i8 = 0; i8 < 8; i8++) {
            const float* hb = sh + (half * 8 + i8) * H;
            #pragma unroll
            for (int g = 0; g < 4; g++) {
                float s = 0.f;
                #pragma unroll
                for (int i = 0; i < 8; i++) s += w[g][i] * hb[lane + i * 32];
                acc[g] = wreduce(s);
            }
            if (lane == i8) {
                float ig = acc[0] + gi0;
                float fg = acc[1] + gi1;
                float gg = acc[2] + gi2;
                float og = acc[3] + gi3;
                float cn = sig_f(fg) * creg + sig_f(ig) * tanh_f(gg);
                float hn = sig_f(og) * tanh_f(cn);
                creg = cn;
                int bb = half * 8 + i8;
                g_c_all[(size_t)(t + 1) * B * H + bb * H + j] = cn;
                g_h_all[(size_t)(t + 1) * B * H + bb * H + j] = hn;
            }
        }

        // grid barrier (monotonic counter; reset by k_prep each replay)
        __syncthreads();
        if (tid == 0) {
            __threadfence();
            atomicAdd(&g_barc, 1u);
            unsigned target = (unsigned)CHAIN_BLOCKS * (unsigned)(t + 1);
            while (*(volatile unsigned*)&g_barc < target) __nanosleep(32);
            __threadfence();
        }
        __syncthreads();
    }
}

// ---------------- dec_feat batched GEMM: [1600,512]x[512,256] --------------
__global__ void __launch_bounds__(256)
k_dec_gemm(const float* __restrict__ bs_) {
    __shared__ float As[64][17];
    __shared__ float Bs[16][64];
    const int m0 = blockIdx.y * 64;
    const int n0 = blockIdx.x * 64;
    const int tid = threadIdx.x;
    const int tx = tid & 15, ty = tid >> 4;
    float acc[4][4] = {};
    for (int k0 = 0; k0 < 512; k0 += 16) {
        for (int i = tid; i < 64 * 16; i += 256) {
            int m = i >> 4, k = i & 15;
            int r = m0 + m;
            int t = r >> 4, bb = r & 15;
            int kk = k0 + k;
            float v = (kk < 256)
                ? g_h_all[(size_t)(t + 1) * B * H + bb * H + kk]
                : g_c_all[(size_t)(t + 1) * B * H + bb * H + kk - 256];
            As[m][k] = v;
        }
        for (int i = tid; i < 16 * 64; i += 256) {
            int k = i >> 6, n = i & 63;
            Bs[k][n] = g_WsT[(size_t)(k0 + k) * 256 + n0 + n];
        }
        __syncthreads();
        #pragma unroll
        for (int kk = 0; kk < 16; kk++) {
            float a0 = As[ty * 4 + 0][kk];
            float a1 = As[ty * 4 + 1][kk];
            float a2 = As[ty * 4 + 2][kk];
            float a3 = As[ty * 4 + 3][kk];
            float4 b4 = *(const float4*)&Bs[kk][tx * 4];
            acc[0][0] += a0 * b4.x; acc[0][1] += a0 * b4.y; acc[0][2] += a0 * b4.z; acc[0][3] += a0 * b4.w;
            acc[1][0] += a1 * b4.x; acc[1][1] += a1 * b4.y; acc[1][2] += a1 * b4.z; acc[1][3] += a1 * b4.w;
            acc[2][0] += a2 * b4.x; acc[2][1] += a2 * b4.y; acc[2][2] += a2 * b4.z; acc[2][3] += a2 * b4.w;
            acc[3][0] += a3 * b4.x; acc[3][1] += a3 * b4.y; acc[3][2] += a3 * b4.z; acc[3][3] += a3 * b4.w;
        }
        __syncthreads();
    }
    #pragma unroll
    for (int i = 0; i < 4; i++) {
        int r = m0 + ty * 4 + i;
        #pragma unroll
        for (int j = 0; j < 4; j++) {
            int n = n0 + tx * 4 + j;
            g_dec_all[(size_t)r * 256 + n] = acc[i][j] + bs_[n];
        }
    }
}

// ---------------- batched e-scores: warp per (b,l), loop t -----------------
__global__ void __launch_bounds__(256)
k_escore_all(const float* __restrict__ v) {
    const int tid = threadIdx.x;
    const int lane = tid & 31, wid = tid >> 5;
    const int gwarp = blockIdx.x * 8 + wid;     // [0, 32768)
    const int b = gwarp >> 11;                  // 2048 warps per b
    const int l = gwarp & 2047;

    const float4* ef4 = (const float4*)(g_enc_feat + ((size_t)(b * L + l)) * H);
    const float4* v4 = (const float4*)v;
    float4 ea = ef4[lane * 2], eb = ef4[lane * 2 + 1];
    float4 sva = v4[lane * 2], svb = v4[lane * 2 + 1];

    float* eout = g_e_tr + ((size_t)(b * L + l)) * 128;

    #pragma unroll 1
    for (int c = 0; c < 4; c++) {
        float ereg = 0.f;
        int tmax = T_STEPS - c * 32;
        if (tmax > 32) tmax = 32;
        #pragma unroll 1
        for (int tt = 0; tt < tmax; tt++) {
            int t = c * 32 + tt;
            const float4* d4 = (const float4*)(g_dec_all + (size_t)(t * B + b) * H);
            float4 dfa = d4[lane * 2], dfb = d4[lane * 2 + 1];
            float s = sva.x * tanh_f(ea.x + dfa.x)
                    + sva.y * tanh_f(ea.y + dfa.y)
                    + sva.z * tanh_f(ea.z + dfa.z)
                    + sva.w * tanh_f(ea.w + dfa.w)
                    + svb.x * tanh_f(eb.x + dfb.x)
                    + svb.y * tanh_f(eb.y + dfb.y)
                    + svb.z * tanh_f(eb.z + dfb.z)
                    + svb.w * tanh_f(eb.w + dfb.w);
            s = wreduce(s);
            if (tt == lane) ereg = s;
        }
        if (c * 32 + lane < T_STEPS) eout[c * 32 + lane] = ereg;
    }
}

// ---------------- batched softmax: block per (t,b) -------------------------
__global__ void __launch_bounds__(256)
k_softmax_all(const float* __restrict__ mask, float* __restrict__ o_attn) {
    __shared__ float red[16];
    const int r = blockIdx.x;         // r = t*B + b
    const int t = r >> 4, b = r & 15;
    const int tid = threadIdx.x;
    const int lane = tid & 31, wid = tid >> 5;

    const float* mrow = mask + (size_t)b * L;

    float ev[8], mv[8];
    float mx = -3.4e38f;
    #pragma unroll
    for (int i = 0; i < 8; i++) {
        int l = tid + i * 256;
        ev[i] = g_e_tr[((size_t)(b * L + l)) * 128 + t];
        mv[i] = mrow[l];
        mx = fmaxf(mx, ev[i]);
    }
    mx = wmax(mx);
    if (lane == 0) red[wid] = mx;
    __syncthreads();
    mx = red[0];
    #pragma unroll
    for (int i = 1; i < 8; i++) mx = fmaxf(mx, red[i]);

    float pv[8];
    float s = 0.f;
    #pragma unroll
    for (int i = 0; i < 8; i++) {
        pv[i] = __expf(ev[i] - mx) * mv[i];
        s += pv[i];
    }
    s = wreduce(s);
    if (lane == 0) red[8 + wid] = s;
    __syncthreads();
    s = 0.f;
    #pragma unroll
    for (int i = 0; i < 8; i++) s += red[8 + i];
    float inv = __fdividef(1.f, s);
    #pragma unroll
    for (int i = 0; i < 8; i++)
        o_attn[(size_t)r * L + tid + i * 256] = pv[i] * inv;
}

// ---------------- ctx batched GEMM per b: [128(t),2048]x[2048,512] ---------
__global__ void __launch_bounds__(256)
k_ctx_gemm(const float* __restrict__ enc, const float* __restrict__ o_attn) {
    __shared__ __align__(16) float Ast[16][132];
    __shared__ __align__(16) float Bs[16][64];
    const int tid = threadIdx.x;
    const int b = blockIdx.y;
    const int n0 = blockIdx.x * 64;
    const int tx = tid & 15, ty = tid >> 4;
    unsigned long long acc[4][4];
    #pragma unroll
    for (int p = 0; p < 4; p++)
        #pragma unroll
        for (int n = 0; n < 4; n++) acc[p][n] = 0ull;

    for (int k0 = 0; k0 < L; k0 += 16) {
        __syncthreads();
        #pragma unroll
        for (int u = 0; u < 2; u++) {
            int idx = u * 256 + tid;
            int row = idx >> 2, q = idx & 3;   // row = t (0..127)
            float4 f = make_float4(0.f, 0.f, 0.f, 0.f);
            if (row < T_STEPS)
                f = *(const float4*)(o_attn + ((size_t)(row * B + b)) * L + k0 + q * 4);
            Ast[q * 4 + 0][row] = f.x;
            Ast[q * 4 + 1][row] = f.y;
            Ast[q * 4 + 2][row] = f.z;
            Ast[q * 4 + 3][row] = f.w;
        }
        {
            int kk = tid >> 4, n4 = (tid & 15) * 4;
            *(float4*)&Bs[kk][n4] =
                *(const float4*)(enc + ((size_t)(b * L + k0 + kk)) * (2 * H) + n0 + n4);
        }
        __syncthreads();
        #pragma unroll
        for (int kk = 0; kk < 16; kk++) {
            unsigned long long a2[4];
            #pragma unroll
            for (int p = 0; p < 4; p++)
                a2[p] = *(const unsigned long long*)&Ast[kk][ty * 8 + p * 2];
            float4 b4 = *(const float4*)&Bs[kk][tx * 4];
            unsigned long long bb[4];
            bb[0] = pack2(b4.x, b4.x); bb[1] = pack2(b4.y, b4.y);
            bb[2] = pack2(b4.z, b4.z); bb[3] = pack2(b4.w, b4.w);
            #pragma unroll
            for (int p = 0; p < 4; p++)
                #pragma unroll
                for (int n = 0; n < 4; n++)
                    fma2(acc[p][n], a2[p], bb[n]);
        }
    }
    #pragma unroll
    for (int p = 0; p < 4; p++) {
        int t = ty * 8 + p * 2;
        #pragma unroll
        for (int n = 0; n < 4; n++) {
            float2 f = unpack2(acc[p][n]);
            int col = n0 + tx * 4 + n;
            if (t < T_STEPS)
                g_ctx_all[(size_t)(t * B + b) * (2 * H) + col] = f.x;
            if (t + 1 < T_STEPS)
                g_ctx_all[(size_t)((t + 1) * B + b) * (2 * H) + col] = f.y;
        }
    }
}

// ---------------- out batched GEMM: [1600,768]x[768,256] -------------------
__global__ void __launch_bounds__(256)
k_out_gemm(const float* __restrict__ bout, float* __restrict__ o_out) {
    __shared__ float As[64][17];
    __shared__ float Bs[16][64];
    const int m0 = blockIdx.y * 64;
    const int n0 = blockIdx.x * 64;
    const int tid = threadIdx.x;
    const int tx = tid & 15, ty = tid >> 4;
    float acc[4][4] = {};
    for (int k0 = 0; k0 < 768; k0 += 16) {
        for (int i = tid; i < 64 * 16; i += 256) {
            int m = i >> 4, k = i & 15;
            int r = m0 + m;
            int t = r >> 4, bb = r & 15;
            int kk = k0 + k;
            float v = (kk < 256)
                ? g_h_all[(size_t)(t + 1) * B * H + bb * H + kk]
                : g_ctx_all[(size_t)r * 512 + kk - 256];
            As[m][k] = v;
        }
        for (int i = tid; i < 16 * 64; i += 256) {
            int k = i >> 6, n = i & 63;
            Bs[k][n] = g_WoutT[(size_t)(k0 + k) * 256 + n0 + n];
        }
        __syncthreads();
        #pragma unroll
        for (int kk = 0; kk < 16; kk++) {
            float a0 = As[ty * 4 + 0][kk];
            float a1 = As[ty * 4 + 1][kk];
            float a2 = As[ty * 4 + 2][kk];
            float a3 = As[ty * 4 + 3][kk];
            float4 b4 = *(const float4*)&Bs[kk][tx * 4];
            acc[0][0] += a0 * b4.x; acc[0][1] += a0 * b4.y; acc[0][2] += a0 * b4.z; acc[0][3] += a0 * b4.w;
            acc[1][0] += a1 * b4.x; acc[1][1] += a1 * b4.y; acc[1][2] += a1 * b4.z; acc[1][3] += a1 * b4.w;
            acc[2][0] += a2 * b4.x; acc[2][1] += a2 * b4.y; acc[2][2] += a2 * b4.z; acc[2][3] += a2 * b4.w;
            acc[3][0] += a3 * b4.x; acc[3][1] += a3 * b4.y; acc[3][2] += a3 * b4.z; acc[3][3] += a3 * b4.w;
        }
        __syncthreads();
    }
    #pragma unroll
    for (int i = 0; i < 4; i++) {
        int r = m0 + ty * 4 + i;
        #pragma unroll
        for (int j = 0; j < 4; j++) {
            int n = n0 + tx * 4 + j;
            o_out[(size_t)r * 256 + n] = acc[i][j] + bout[n];
        }
    }
}

// ---------------- p_gen batched + h_f/c_f ----------------------------------
__global__ void __launch_bounds__(256)
k_pgen(const float* __restrict__ Wpg, const float* __restrict__ bpg,
       float* __restrict__ o_pgen, float* __restrict__ o_hf, float* __restrict__ o_cf) {
    const int tid = threadIdx.x;
    const int lane = tid & 31, wid = tid >> 5;
    const int blk = blockIdx.x;

    if (blk < 200) {
        const int r = blk * 8 + wid;     // [0, 1600)
        const int t = r >> 4, bb = r & 15;
        float s = 0.f;
        for (int k = lane; k < 4 * H + E; k += 32) {
            float cv;
            if (k < 2 * H) cv = g_ctx_all[(size_t)r * 512 + k];
            else if (k < 3 * H) cv = g_h_all[(size_t)(t + 1) * B * H + bb * H + k - 2 * H];
            else if (k < 4 * H) cv = g_c_all[(size_t)(t + 1) * B * H + bb * H + k - 3 * H];
            else cv = g_x_all[(size_t)r * E + k - 4 * H];
            s += cv * Wpg[k];
        }
        s = wreduce(s);
        if (lane == 0) o_pgen[r] = sig_f(s + bpg[0]);
    } else {
        for (int i = (blk - 200) * 256 + tid; i < B * H; i += 512) {
            o_hf[i] = g_h_all[(size_t)T_STEPS * B * H + i];
            o_cf[i] = g_c_all[(size_t)T_STEPS * B * H + i];
        }
    }
}

// ---------------- host launcher ----------------
extern "C" void kernel_launch(void* const* d_in, const int* in_sizes, int n_in,
                              void* d_out, int out_size) {
    const float* dec_in = (const float*)d_in[0];
    const float* h0     = (const float*)d_in[1];
    const float* c0     = (const float*)d_in[2];
    const float* enc    = (const float*)d_in[3];
    const float* mask   = (const float*)d_in[4];
    const float* Wh     = (const float*)d_in[5];
    const float* bh     = (const float*)d_in[6];
    const float* Ws_    = (const float*)d_in[7];
    const float* bs_    = (const float*)d_in[8];
    const float* v      = (const float*)d_in[9];
    const float* Wx     = (const float*)d_in[10];
    const float* bx     = (const float*)d_in[11];
    const float* Wih    = (const float*)d_in[12];
    const float* bih    = (const float*)d_in[13];
    const float* Whh    = (const float*)d_in[14];
    const float* bhh    = (const float*)d_in[15];
    const float* Wpg    = (const float*)d_in[16];
    const float* bpg    = (const float*)d_in[17];
    const float* Wout   = (const float*)d_in[18];
    const float* bout   = (const float*)d_in[19];

    float* out = (float*)d_out;
    float* o_outputs = out;                                  // [T,B,H]
    float* o_hf = o_outputs + (size_t)T_STEPS * B * H;       // [B,H]
    float* o_cf = o_hf + B * H;                              // [B,H]
    float* o_attn = o_cf + B * H;                            // [T,B,L]
    float* o_pgen = o_attn + (size_t)T_STEPS * B * L;        // [T,B,1]

    k_prep<<<1808, 256>>>(Wh, Ws_, Wout, h0, c0);
    k_pre_x<<<T_STEPS * B, 256>>>(dec_in, Wx, bx, Wih, bih, bhh);
    k_encfeat2<<<dim3(4, 256), 256>>>(enc, bh);

    k_chain<<<CHAIN_BLOCKS, 256>>>(Whh);

    k_dec_gemm<<<dim3(4, 25), 256>>>(bs_);
    k_escore_all<<<4096, 256>>>(v);
    k_softmax_all<<<1600, 256>>>(mask, o_attn);
    k_ctx_gemm<<<dim3(8, 16), 256>>>(enc, o_attn);
    k_out_gemm<<<dim3(4, 25), 256>>>(bout, o_outputs);
    k_pgen<<<202, 256>>>(Wpg, bpg, o_pgen, o_hf, o_cf);
}

// round 9
// speedup vs baseline: 11.6934x; 1.7118x over previous
#include <cuda_runtime.h>
#include <cstdint>

#define T_STEPS 100
#define B 16
#define E 128
#define H 256
#define L 2048
#define CHAIN_BLOCKS 64

// ---------------- device scratch (static allocations only) ----------------
__device__ float g_enc_feat[B * L * H];                 // 33.5 MB
__device__ float g_WhT[512 * 256];
__device__ float g_WsT[512 * 256];
__device__ float g_WoutT[768 * 256];
__device__ float g_WihT[128 * 1024];
__device__ float g_WxT[128 * 128];
__device__ float g_x_all[T_STEPS * B * E];
__device__ float g_gi[T_STEPS * B * 4 * H];
__device__ float g_h_all[(T_STEPS + 1) * B * H];
__device__ float g_c_all[(T_STEPS + 1) * B * H];
__device__ float g_dec_all[T_STEPS * B * H];
__device__ float g_ctx_all[T_STEPS * B * 2 * H];
__device__ float g_e_tr[B * L * 128];                   // [b][l][t(pad128)]
__device__ unsigned g_barc;

// ---------------- fast math helpers ----------------
__device__ __forceinline__ float tanh_f(float x) {
    float e = __expf(2.f * x);
    return 1.f - __fdividef(2.f, e + 1.f);
}
__device__ __forceinline__ float sig_f(float x) {
    return __fdividef(1.f, 1.f + __expf(-x));
}
__device__ __forceinline__ float wreduce(float s) {
    #pragma unroll
    for (int off = 16; off; off >>= 1) s += __shfl_xor_sync(0xffffffffu, s, off);
    return s;
}
__device__ __forceinline__ float wmax(float s) {
    #pragma unroll
    for (int off = 16; off; off >>= 1) s = fmaxf(s, __shfl_xor_sync(0xffffffffu, s, off));
    return s;
}
__device__ __forceinline__ unsigned long long pack2(float x, float y) {
    unsigned long long r;
    asm("mov.b64 %0, {%1, %2};" : "=l"(r) : "f"(x), "f"(y));
    return r;
}
__device__ __forceinline__ void fma2(unsigned long long& d, unsigned long long a, unsigned long long b) {
    asm("fma.rn.f32x2 %0, %1, %2, %3;" : "=l"(d) : "l"(a), "l"(b), "l"(d));
}
__device__ __forceinline__ float2 unpack2(unsigned long long v) {
    float2 f;
    asm("mov.b64 {%0, %1}, %2;" : "=f"(f.x), "=f"(f.y) : "l"(v));
    return f;
}

// ---------------- prep: all transposes + h/c init + barrier reset ----------
// blocks: [0,512) WhT | [512,1024) WsT | [1024,1792) WoutT |
//         [1792,2304) WihT | [2304,2368) WxT | [2368,2384) init h/c
__global__ void k_prep(const float* __restrict__ Wh, const float* __restrict__ Ws_,
                       const float* __restrict__ Wout, const float* __restrict__ Wih,
                       const float* __restrict__ Wx,
                       const float* __restrict__ h0, const float* __restrict__ c0) {
    int blk = blockIdx.x, tid = threadIdx.x;
    if (blk == 0 && tid == 0) g_barc = 0u;
    if (blk < 512) {
        int i = blk * 256 + tid;
        int j = i & 255, k = i >> 8;
        g_WhT[i] = Wh[j * 512 + k];
    } else if (blk < 1024) {
        int i = (blk - 512) * 256 + tid;
        int j = i & 255, k = i >> 8;
        g_WsT[i] = Ws_[j * 512 + k];
    } else if (blk < 1792) {
        int i = (blk - 1024) * 256 + tid;
        int j = i & 255, k = i >> 8;
        g_WoutT[i] = Wout[j * 768 + k];
    } else if (blk < 2304) {
        int i = (blk - 1792) * 256 + tid;
        int j = i & 1023, k = i >> 10;
        g_WihT[i] = Wih[j * 128 + k];
    } else if (blk < 2368) {
        int i = (blk - 2304) * 256 + tid;
        int j = i & 127, k = i >> 7;
        g_WxT[i] = Wx[j * (2 * H + E) + k];
    } else {
        int i = (blk - 2368) * 256 + tid;
        g_h_all[i] = h0[i];
        g_c_all[i] = c0[i];
    }
}

// ---------------- x GEMM: [1600,128] = dec_in @ WxT + bx -------------------
__global__ void __launch_bounds__(256)
k_xg(const float* __restrict__ Din, const float* __restrict__ bx) {
    __shared__ float As[64][17];
    __shared__ float Bs[16][64];
    const int m0 = blockIdx.y * 64;
    const int n0 = blockIdx.x * 64;
    const int tid = threadIdx.x;
    const int tx = tid & 15, ty = tid >> 4;
    float acc[4][4] = {};
    for (int k0 = 0; k0 < 128; k0 += 16) {
        for (int i = tid; i < 64 * 16; i += 256) {
            int m = i >> 4, k = i & 15;
            As[m][k] = Din[(size_t)(m0 + m) * 128 + k0 + k];
        }
        for (int i = tid; i < 16 * 64; i += 256) {
            int k = i >> 6, n = i & 63;
            Bs[k][n] = g_WxT[(size_t)(k0 + k) * 128 + n0 + n];
        }
        __syncthreads();
        #pragma unroll
        for (int kk = 0; kk < 16; kk++) {
            float a0 = As[ty * 4 + 0][kk], a1 = As[ty * 4 + 1][kk];
            float a2 = As[ty * 4 + 2][kk], a3 = As[ty * 4 + 3][kk];
            float4 b4 = *(const float4*)&Bs[kk][tx * 4];
            acc[0][0] += a0 * b4.x; acc[0][1] += a0 * b4.y; acc[0][2] += a0 * b4.z; acc[0][3] += a0 * b4.w;
            acc[1][0] += a1 * b4.x; acc[1][1] += a1 * b4.y; acc[1][2] += a1 * b4.z; acc[1][3] += a1 * b4.w;
            acc[2][0] += a2 * b4.x; acc[2][1] += a2 * b4.y; acc[2][2] += a2 * b4.z; acc[2][3] += a2 * b4.w;
            acc[3][0] += a3 * b4.x; acc[3][1] += a3 * b4.y; acc[3][2] += a3 * b4.z; acc[3][3] += a3 * b4.w;
        }
        __syncthreads();
    }
    #pragma unroll
    for (int i = 0; i < 4; i++) {
        int r = m0 + ty * 4 + i;
        #pragma unroll
        for (int j = 0; j < 4; j++) {
            int n = n0 + tx * 4 + j;
            g_x_all[(size_t)r * 128 + n] = acc[i][j] + bx[n];
        }
    }
}

// ---------------- gi GEMM: [1600,1024] = x_all @ WihT + bih + bhh ----------
__global__ void __launch_bounds__(256)
k_gig(const float* __restrict__ bih, const float* __restrict__ bhh) {
    __shared__ float As[64][17];
    __shared__ float Bs[16][64];
    const int m0 = blockIdx.y * 64;
    const int n0 = blockIdx.x * 64;
    const int tid = threadIdx.x;
    const int tx = tid & 15, ty = tid >> 4;
    float acc[4][4] = {};
    for (int k0 = 0; k0 < 128; k0 += 16) {
        for (int i = tid; i < 64 * 16; i += 256) {
            int m = i >> 4, k = i & 15;
            As[m][k] = g_x_all[(size_t)(m0 + m) * 128 + k0 + k];
        }
        for (int i = tid; i < 16 * 64; i += 256) {
            int k = i >> 6, n = i & 63;
            Bs[k][n] = g_WihT[(size_t)(k0 + k) * 1024 + n0 + n];
        }
        __syncthreads();
        #pragma unroll
        for (int kk = 0; kk < 16; kk++) {
            float a0 = As[ty * 4 + 0][kk], a1 = As[ty * 4 + 1][kk];
            float a2 = As[ty * 4 + 2][kk], a3 = As[ty * 4 + 3][kk];
            float4 b4 = *(const float4*)&Bs[kk][tx * 4];
            acc[0][0] += a0 * b4.x; acc[0][1] += a0 * b4.y; acc[0][2] += a0 * b4.z; acc[0][3] += a0 * b4.w;
            acc[1][0] += a1 * b4.x; acc[1][1] += a1 * b4.y; acc[1][2] += a1 * b4.z; acc[1][3] += a1 * b4.w;
            acc[2][0] += a2 * b4.x; acc[2][1] += a2 * b4.y; acc[2][2] += a2 * b4.z; acc[2][3] += a2 * b4.w;
            acc[3][0] += a3 * b4.x; acc[3][1] += a3 * b4.y; acc[3][2] += a3 * b4.z; acc[3][3] += a3 * b4.w;
        }
        __syncthreads();
    }
    #pragma unroll
    for (int i = 0; i < 4; i++) {
        int r = m0 + ty * 4 + i;
        #pragma unroll
        for (int j = 0; j < 4; j++) {
            int n = n0 + tx * 4 + j;
            g_gi[(size_t)r * 1024 + n] = acc[i][j] + bih[n] + bhh[n];
        }
    }
}

// ================= FAT kernel: chain (blocks 0..63) ∥ encfeat (64..1087) ===
__global__ void __launch_bounds__(256)
k_fat(const float* __restrict__ Whh, const float* __restrict__ ES,
      const float* __restrict__ bh) {
    __shared__ __align__(16) float smem_u[4096];   // 16 KB union
    const int tid = threadIdx.x;

    if (blockIdx.x < CHAIN_BLOCKS) {
        // ---------------- persistent LSTM chain ----------------
        float* sh = smem_u;   // 4096 floats = h(t)
        const int lane = tid & 31, wid = tid >> 5;
        const int gw = blockIdx.x * 8 + wid;
        const int j = gw >> 1;
        const int half = gw & 1;

        float w[4][8];
        #pragma unroll
        for (int g = 0; g < 4; g++)
            #pragma unroll
            for (int i = 0; i < 8; i++)
                w[g][i] = Whh[(size_t)(g * H + j) * H + lane + i * 32];

        float creg = 0.f;
        if (lane < 8) creg = g_c_all[(half * 8 + lane) * H + j];

        for (int t = 0; t < T_STEPS; t++) {
            {
                const float4* hsrc4 = (const float4*)(g_h_all + (size_t)t * B * H);
                float4* sh4 = (float4*)sh;
                #pragma unroll
                for (int i = 0; i < 4; i++) sh4[tid + i * 256] = __ldcg(hsrc4 + tid + i * 256);
            }
            __syncthreads();

            float gi0 = 0.f, gi1 = 0.f, gi2 = 0.f, gi3 = 0.f;
            if (lane < 8) {
                const float* gi = g_gi + (size_t)(t * B + half * 8 + lane) * 4 * H;
                gi0 = gi[j]; gi1 = gi[H + j]; gi2 = gi[2 * H + j]; gi3 = gi[3 * H + j];
            }

            float acc[4];
            #pragma unroll 2
            for (int i8 = 0; i8 < 8; i8++) {
                const float* hb = sh + (half * 8 + i8) * H;
                #pragma unroll
                for (int g = 0; g < 4; g++) {
                    float s = 0.f;
                    #pragma unroll
                    for (int i = 0; i < 8; i++) s += w[g][i] * hb[lane + i * 32];
                    acc[g] = wreduce(s);
                }
                if (lane == i8) {
                    float ig = acc[0] + gi0;
                    float fg = acc[1] + gi1;
                    float gg = acc[2] + gi2;
                    float og = acc[3] + gi3;
                    float cn = sig_f(fg) * creg + sig_f(ig) * tanh_f(gg);
                    float hn = sig_f(og) * tanh_f(cn);
                    creg = cn;
                    int bb = half * 8 + i8;
                    g_c_all[(size_t)(t + 1) * B * H + bb * H + j] = cn;
                    g_h_all[(size_t)(t + 1) * B * H + bb * H + j] = hn;
                }
            }

            __syncthreads();
            if (tid == 0) {
                __threadfence();
                atomicAdd(&g_barc, 1u);
                unsigned target = (unsigned)CHAIN_BLOCKS * (unsigned)(t + 1);
                while (*(volatile unsigned*)&g_barc < target) __nanosleep(32);
                __threadfence();
            }
            __syncthreads();
        }
    } else {
        // ---------------- enc_feat GEMM tile ----------------
        float (*Ast)[132] = (float(*)[132])smem_u;                 // 2112 floats
        float (*Bs)[64] = (float(*)[64])(smem_u + 2112);           // 1024 floats
        const int eb = blockIdx.x - CHAIN_BLOCKS;                  // [0,1024)
        const int m0 = (eb >> 2) * 128;
        const int n0 = (eb & 3) * 64;
        const int tx = tid & 15, ty = tid >> 4;
        unsigned long long acc[4][4];
        #pragma unroll
        for (int p = 0; p < 4; p++)
            #pragma unroll
            for (int n = 0; n < 4; n++) acc[p][n] = 0ull;

        for (int k0 = 0; k0 < 512; k0 += 16) {
            __syncthreads();
            #pragma unroll
            for (int u = 0; u < 2; u++) {
                int idx = u * 256 + tid;
                int row = idx >> 2, q = idx & 3;
                float4 f = *(const float4*)(ES + (size_t)(m0 + row) * 512 + k0 + q * 4);
                Ast[q * 4 + 0][row] = f.x;
                Ast[q * 4 + 1][row] = f.y;
                Ast[q * 4 + 2][row] = f.z;
                Ast[q * 4 + 3][row] = f.w;
            }
            {
                int kk = tid >> 4, n4 = (tid & 15) * 4;
                *(float4*)&Bs[kk][n4] = *(const float4*)(g_WhT + (size_t)(k0 + kk) * 256 + n0 + n4);
            }
            __syncthreads();
            #pragma unroll
            for (int kk = 0; kk < 16; kk++) {
                unsigned long long a2[4];
                #pragma unroll
                for (int p = 0; p < 4; p++)
                    a2[p] = *(const unsigned long long*)&Ast[kk][ty * 8 + p * 2];
                float4 b4 = *(const float4*)&Bs[kk][tx * 4];
                unsigned long long bb[4];
                bb[0] = pack2(b4.x, b4.x); bb[1] = pack2(b4.y, b4.y);
                bb[2] = pack2(b4.z, b4.z); bb[3] = pack2(b4.w, b4.w);
                #pragma unroll
                for (int p = 0; p < 4; p++)
                    #pragma unroll
                    for (int n = 0; n < 4; n++)
                        fma2(acc[p][n], a2[p], bb[n]);
            }
        }
        #pragma unroll
        for (int p = 0; p < 4; p++) {
            int m = m0 + ty * 8 + p * 2;
            #pragma unroll
            for (int n = 0; n < 4; n++) {
                float2 f = unpack2(acc[p][n]);
                int col = n0 + tx * 4 + n;
                float bv = bh[col];
                g_enc_feat[(size_t)m * 256 + col] = f.x + bv;
                g_enc_feat[(size_t)(m + 1) * 256 + col] = f.y + bv;
            }
        }
    }
}

// ---------------- dec_feat batched GEMM: [1600,512]x[512,256] --------------
__global__ void __launch_bounds__(256)
k_dec_gemm(const float* __restrict__ bs_) {
    __shared__ float As[64][17];
    __shared__ float Bs[16][64];
    const int m0 = blockIdx.y * 64;
    const int n0 = blockIdx.x * 64;
    const int tid = threadIdx.x;
    const int tx = tid & 15, ty = tid >> 4;
    float acc[4][4] = {};
    for (int k0 = 0; k0 < 512; k0 += 16) {
        for (int i = tid; i < 64 * 16; i += 256) {
            int m = i >> 4, k = i & 15;
            int r = m0 + m;
            int t = r >> 4, bb = r & 15;
            int kk = k0 + k;
            float v = (kk < 256)
                ? g_h_all[(size_t)(t + 1) * B * H + bb * H + kk]
                : g_c_all[(size_t)(t + 1) * B * H + bb * H + kk - 256];
            As[m][k] = v;
        }
        for (int i = tid; i < 16 * 64; i += 256) {
            int k = i >> 6, n = i & 63;
            Bs[k][n] = g_WsT[(size_t)(k0 + k) * 256 + n0 + n];
        }
        __syncthreads();
        #pragma unroll
        for (int kk = 0; kk < 16; kk++) {
            float a0 = As[ty * 4 + 0][kk], a1 = As[ty * 4 + 1][kk];
            float a2 = As[ty * 4 + 2][kk], a3 = As[ty * 4 + 3][kk];
            float4 b4 = *(const float4*)&Bs[kk][tx * 4];
            acc[0][0] += a0 * b4.x; acc[0][1] += a0 * b4.y; acc[0][2] += a0 * b4.z; acc[0][3] += a0 * b4.w;
            acc[1][0] += a1 * b4.x; acc[1][1] += a1 * b4.y; acc[1][2] += a1 * b4.z; acc[1][3] += a1 * b4.w;
            acc[2][0] += a2 * b4.x; acc[2][1] += a2 * b4.y; acc[2][2] += a2 * b4.z; acc[2][3] += a2 * b4.w;
            acc[3][0] += a3 * b4.x; acc[3][1] += a3 * b4.y; acc[3][2] += a3 * b4.z; acc[3][3] += a3 * b4.w;
        }
        __syncthreads();
    }
    #pragma unroll
    for (int i = 0; i < 4; i++) {
        int r = m0 + ty * 4 + i;
        #pragma unroll
        for (int j = 0; j < 4; j++) {
            int n = n0 + tx * 4 + j;
            g_dec_all[(size_t)r * 256 + n] = acc[i][j] + bs_[n];
        }
    }
}

// ---------------- batched e-scores: warp per (b,l), loop t -----------------
__global__ void __launch_bounds__(256)
k_escore_all(const float* __restrict__ v) {
    const int tid = threadIdx.x;
    const int lane = tid & 31, wid = tid >> 5;
    const int gwarp = blockIdx.x * 8 + wid;
    const int b = gwarp >> 11;
    const int l = gwarp & 2047;

    const float4* ef4 = (const float4*)(g_enc_feat + ((size_t)(b * L + l)) * H);
    const float4* v4 = (const float4*)v;
    float4 ea = ef4[lane * 2], eb = ef4[lane * 2 + 1];
    float4 sva = v4[lane * 2], svb = v4[lane * 2 + 1];

    float* eout = g_e_tr + ((size_t)(b * L + l)) * 128;

    #pragma unroll 1
    for (int c = 0; c < 4; c++) {
        float ereg = 0.f;
        int tmax = T_STEPS - c * 32;
        if (tmax > 32) tmax = 32;
        #pragma unroll 1
        for (int tt = 0; tt < tmax; tt++) {
            int t = c * 32 + tt;
            const float4* d4 = (const float4*)(g_dec_all + (size_t)(t * B + b) * H);
            float4 dfa = d4[lane * 2], dfb = d4[lane * 2 + 1];
            float s = sva.x * tanh_f(ea.x + dfa.x)
                    + sva.y * tanh_f(ea.y + dfa.y)
                    + sva.z * tanh_f(ea.z + dfa.z)
                    + sva.w * tanh_f(ea.w + dfa.w)
                    + svb.x * tanh_f(eb.x + dfb.x)
                    + svb.y * tanh_f(eb.y + dfb.y)
                    + svb.z * tanh_f(eb.z + dfb.z)
                    + svb.w * tanh_f(eb.w + dfb.w);
            s = wreduce(s);
            if (tt == lane) ereg = s;
        }
        if (c * 32 + lane < T_STEPS) eout[c * 32 + lane] = ereg;
    }
}

// ---------------- batched softmax: block per (t,b) -------------------------
__global__ void __launch_bounds__(256)
k_softmax_all(const float* __restrict__ mask, float* __restrict__ o_attn) {
    __shared__ float red[16];
    const int r = blockIdx.x;
    const int t = r >> 4, b = r & 15;
    const int tid = threadIdx.x;
    const int lane = tid & 31, wid = tid >> 5;

    const float* mrow = mask + (size_t)b * L;

    float ev[8], mv[8];
    float mx = -3.4e38f;
    #pragma unroll
    for (int i = 0; i < 8; i++) {
        int l = tid + i * 256;
        ev[i] = g_e_tr[((size_t)(b * L + l)) * 128 + t];
        mv[i] = mrow[l];
        mx = fmaxf(mx, ev[i]);
    }
    mx = wmax(mx);
    if (lane == 0) red[wid] = mx;
    __syncthreads();
    mx = red[0];
    #pragma unroll
    for (int i = 1; i < 8; i++) mx = fmaxf(mx, red[i]);

    float pv[8];
    float s = 0.f;
    #pragma unroll
    for (int i = 0; i < 8; i++) {
        pv[i] = __expf(ev[i] - mx) * mv[i];
        s += pv[i];
    }
    s = wreduce(s);
    if (lane == 0) red[8 + wid] = s;
    __syncthreads();
    s = 0.f;
    #pragma unroll
    for (int i = 0; i < 8; i++) s += red[8 + i];
    float inv = __fdividef(1.f, s);
    #pragma unroll
    for (int i = 0; i < 8; i++)
        o_attn[(size_t)r * L + tid + i * 256] = pv[i] * inv;
}

// ---------------- ctx batched GEMM per b: [128(t),2048]x[2048,512] ---------
__global__ void __launch_bounds__(256)
k_ctx_gemm(const float* __restrict__ enc, const float* __restrict__ o_attn) {
    __shared__ __align__(16) float Ast[16][132];
    __shared__ __align__(16) float Bs[16][64];
    const int tid = threadIdx.x;
    const int b = blockIdx.y;
    const int n0 = blockIdx.x * 64;
    const int tx = tid & 15, ty = tid >> 4;
    unsigned long long acc[4][4];
    #pragma unroll
    for (int p = 0; p < 4; p++)
        #pragma unroll
        for (int n = 0; n < 4; n++) acc[p][n] = 0ull;

    for (int k0 = 0; k0 < L; k0 += 16) {
        __syncthreads();
        #pragma unroll
        for (int u = 0; u < 2; u++) {
            int idx = u * 256 + tid;
            int row = idx >> 2, q = idx & 3;
            float4 f = make_float4(0.f, 0.f, 0.f, 0.f);
            if (row < T_STEPS)
                f = *(const float4*)(o_attn + ((size_t)(row * B + b)) * L + k0 + q * 4);
            Ast[q * 4 + 0][row] = f.x;
            Ast[q * 4 + 1][row] = f.y;
            Ast[q * 4 + 2][row] = f.z;
            Ast[q * 4 + 3][row] = f.w;
        }
        {
            int kk = tid >> 4, n4 = (tid & 15) * 4;
            *(float4*)&Bs[kk][n4] =
                *(const float4*)(enc + ((size_t)(b * L + k0 + kk)) * (2 * H) + n0 + n4);
        }
        __syncthreads();
        #pragma unroll
        for (int kk = 0; kk < 16; kk++) {
            unsigned long long a2[4];
            #pragma unroll
            for (int p = 0; p < 4; p++)
                a2[p] = *(const unsigned long long*)&Ast[kk][ty * 8 + p * 2];
            float4 b4 = *(const float4*)&Bs[kk][tx * 4];
            unsigned long long bb[4];
            bb[0] = pack2(b4.x, b4.x); bb[1] = pack2(b4.y, b4.y);
            bb[2] = pack2(b4.z, b4.z); bb[3] = pack2(b4.w, b4.w);
            #pragma unroll
            for (int p = 0; p < 4; p++)
                #pragma unroll
                for (int n = 0; n < 4; n++)
                    fma2(acc[p][n], a2[p], bb[n]);
        }
    }
    #pragma unroll
    for (int p = 0; p < 4; p++) {
        int t = ty * 8 + p * 2;
        #pragma unroll
        for (int n = 0; n < 4; n++) {
            float2 f = unpack2(acc[p][n]);
            int col = n0 + tx * 4 + n;
            if (t < T_STEPS)
                g_ctx_all[(size_t)(t * B + b) * (2 * H) + col] = f.x;
            if (t + 1 < T_STEPS)
                g_ctx_all[(size_t)((t + 1) * B + b) * (2 * H) + col] = f.y;
        }
    }
}

// ---------------- out batched GEMM: [1600,768]x[768,256] -------------------
__global__ void __launch_bounds__(256)
k_out_gemm(const float* __restrict__ bout, float* __restrict__ o_out) {
    __shared__ float As[64][17];
    __shared__ float Bs[16][64];
    const int m0 = blockIdx.y * 64;
    const int n0 = blockIdx.x * 64;
    const int tid = threadIdx.x;
    const int tx = tid & 15, ty = tid >> 4;
    float acc[4][4] = {};
    for (int k0 = 0; k0 < 768; k0 += 16) {
        for (int i = tid; i < 64 * 16; i += 256) {
            int m = i >> 4, k = i & 15;
            int r = m0 + m;
            int t = r >> 4, bb = r & 15;
            int kk = k0 + k;
            float v = (kk < 256)
                ? g_h_all[(size_t)(t + 1) * B * H + bb * H + kk]
                : g_ctx_all[(size_t)r * 512 + kk - 256];
            As[m][k] = v;
        }
        for (int i = tid; i < 16 * 64; i += 256) {
            int k = i >> 6, n = i & 63;
            Bs[k][n] = g_WoutT[(size_t)(k0 + k) * 256 + n0 + n];
        }
        __syncthreads();
        #pragma unroll
        for (int kk = 0; kk < 16; kk++) {
            float a0 = As[ty * 4 + 0][kk], a1 = As[ty * 4 + 1][kk];
            float a2 = As[ty * 4 + 2][kk], a3 = As[ty * 4 + 3][kk];
            float4 b4 = *(const float4*)&Bs[kk][tx * 4];
            acc[0][0] += a0 * b4.x; acc[0][1] += a0 * b4.y; acc[0][2] += a0 * b4.z; acc[0][3] += a0 * b4.w;
            acc[1][0] += a1 * b4.x; acc[1][1] += a1 * b4.y; acc[1][2] += a1 * b4.z; acc[1][3] += a1 * b4.w;
            acc[2][0] += a2 * b4.x; acc[2][1] += a2 * b4.y; acc[2][2] += a2 * b4.z; acc[2][3] += a2 * b4.w;
            acc[3][0] += a3 * b4.x; acc[3][1] += a3 * b4.y; acc[3][2] += a3 * b4.z; acc[3][3] += a3 * b4.w;
        }
        __syncthreads();
    }
    #pragma unroll
    for (int i = 0; i < 4; i++) {
        int r = m0 + ty * 4 + i;
        #pragma unroll
        for (int j = 0; j < 4; j++) {
            int n = n0 + tx * 4 + j;
            o_out[(size_t)r * 256 + n] = acc[i][j] + bout[n];
        }
    }
}

// ---------------- p_gen batched + h_f/c_f ----------------------------------
__global__ void __launch_bounds__(256)
k_pgen(const float* __restrict__ Wpg, const float* __restrict__ bpg,
       float* __restrict__ o_pgen, float* __restrict__ o_hf, float* __restrict__ o_cf) {
    const int tid = threadIdx.x;
    const int lane = tid & 31, wid = tid >> 5;
    const int blk = blockIdx.x;

    if (blk < 200) {
        const int r = blk * 8 + wid;
        const int t = r >> 4, bb = r & 15;
        float s = 0.f;
        for (int k = lane; k < 4 * H + E; k += 32) {
            float cv;
            if (k < 2 * H) cv = g_ctx_all[(size_t)r * 512 + k];
            else if (k < 3 * H) cv = g_h_all[(size_t)(t + 1) * B * H + bb * H + k - 2 * H];
            else if (k < 4 * H) cv = g_c_all[(size_t)(t + 1) * B * H + bb * H + k - 3 * H];
            else cv = g_x_all[(size_t)r * E + k - 4 * H];
            s += cv * Wpg[k];
        }
        s = wreduce(s);
        if (lane == 0) o_pgen[r] = sig_f(s + bpg[0]);
    } else {
        for (int i = (blk - 200) * 256 + tid; i < B * H; i += 512) {
            o_hf[i] = g_h_all[(size_t)T_STEPS * B * H + i];
            o_cf[i] = g_c_all[(size_t)T_STEPS * B * H + i];
        }
    }
}

// ---------------- host launcher ----------------
extern "C" void kernel_launch(void* const* d_in, const int* in_sizes, int n_in,
                              void* d_out, int out_size) {
    const float* dec_in = (const float*)d_in[0];
    const float* h0     = (const float*)d_in[1];
    const float* c0     = (const float*)d_in[2];
    const float* enc    = (const float*)d_in[3];
    const float* mask   = (const float*)d_in[4];
    const float* Wh     = (const float*)d_in[5];
    const float* bh     = (const float*)d_in[6];
    const float* Ws_    = (const float*)d_in[7];
    const float* bs_    = (const float*)d_in[8];
    const float* v      = (const float*)d_in[9];
    const float* Wx     = (const float*)d_in[10];
    const float* bx     = (const float*)d_in[11];
    const float* Wih    = (const float*)d_in[12];
    const float* bih    = (const float*)d_in[13];
    const float* Whh    = (const float*)d_in[14];
    const float* bhh    = (const float*)d_in[15];
    const float* Wpg    = (const float*)d_in[16];
    const float* bpg    = (const float*)d_in[17];
    const float* Wout   = (const float*)d_in[18];
    const float* bout   = (const float*)d_in[19];

    float* out = (float*)d_out;
    float* o_outputs = out;                                  // [T,B,H]
    float* o_hf = o_outputs + (size_t)T_STEPS * B * H;       // [B,H]
    float* o_cf = o_hf + B * H;                              // [B,H]
    float* o_attn = o_cf + B * H;                            // [T,B,L]
    float* o_pgen = o_attn + (size_t)T_STEPS * B * L;        // [T,B,1]

    k_prep<<<2384, 256>>>(Wh, Ws_, Wout, Wih, Wx, h0, c0);
    k_xg<<<dim3(2, 25), 256>>>(dec_in, bx);
    k_gig<<<dim3(16, 25), 256>>>(bih, bhh);

    k_fat<<<CHAIN_BLOCKS + 1024, 256>>>(Whh, enc, bh);

    k_dec_gemm<<<dim3(4, 25), 256>>>(bs_);
    k_escore_all<<<4096, 256>>>(v);
    k_softmax_all<<<1600, 256>>>(mask, o_attn);
    k_ctx_gemm<<<dim3(8, 16), 256>>>(enc, o_attn);
    k_out_gemm<<<dim3(4, 25), 256>>>(bout, o_outputs);
    k_pgen<<<202, 256>>>(Wpg, bpg, o_pgen, o_hf, o_cf);
}